// round 5
// baseline (speedup 1.0000x reference)
#include <cuda_runtime.h>
#include <cuda_bf16.h>
#include <math_constants.h>
#include <cstdint>

#define BB 4
#define TT 2048
#define DD 1024

// =================== scratch (device globals; no allocation) ===============
// Split operand arrays, stored PRE-PERMUTED in mma fragment order.
__device__ float g_Xh[(size_t)BB * TT * DD];
__device__ float g_Xl[(size_t)BB * TT * DD];
__device__ float g_Wh[(size_t)3 * DD * DD];
__device__ float g_Wl[(size_t)3 * DD * DD];
__device__ float g_Qh[(size_t)BB * TT * DD];
__device__ float g_Ql[(size_t)BB * TT * DD];
__device__ float g_Kh[(size_t)BB * TT * DD];
__device__ float g_Kl[(size_t)BB * TT * DD];
__device__ float g_Vh[(size_t)BB * TT * DD];
__device__ float g_Vl[(size_t)BB * TT * DD];
__device__ float g_S [(size_t)BB * TT * TT];
__device__ float g_Sh[(size_t)BB * TT * TT];
__device__ float g_Sl[(size_t)BB * TT * TT];

// ============================ helpers ======================================
__device__ __forceinline__ uint32_t smem_to_u32(const void* p) {
    uint32_t a;
    asm("{ .reg .u64 t; cvta.to.shared.u64 t, %1; cvt.u32.u64 %0, t; }"
        : "=r"(a) : "l"(p));
    return a;
}
__device__ __forceinline__ float to_tf32(float x) {
    float r; asm("cvt.rna.tf32.f32 %0, %1;" : "=f"(r) : "f"(x)); return r;
}

// m16n8k8 tf32 mma, fp32 accumulate (baseline PTX, sm_80+)
__device__ __forceinline__ void mma8(float* d, uint4 a, uint2 b) {
    asm volatile(
        "mma.sync.aligned.m16n8k8.row.col.f32.tf32.tf32.f32 "
        "{%0,%1,%2,%3}, {%4,%5,%6,%7}, {%8,%9}, {%0,%1,%2,%3};"
        : "+f"(d[0]), "+f"(d[1]), "+f"(d[2]), "+f"(d[3])
        : "r"(a.x), "r"(a.y), "r"(a.z), "r"(a.w), "r"(b.x), "r"(b.y));
}

// A-layout (mma A fragment order): region = (m>>4)*(Ck>>3)+(k>>3), 128 floats.
// elem -> region*128 + ((m&7)*4 + (k&3))*4 + ((m>>3)&1) + (((k>>2)&1)<<1)
__device__ __forceinline__ size_t idxA(int M, int K, int Ck) {
    return ((size_t)((M >> 4) * (Ck >> 3) + (K >> 3))) * 128
         + (size_t)(((M & 7) * 4 + (K & 3)) * 4 + ((M >> 3) & 1) + (((K >> 2) & 1) << 1));
}
// B-layout (mma B fragment order): region = (n>>3)*(Ck>>3)+(k>>3), 64 floats.
// elem -> region*64 + ((n&7)*4 + (k&3))*2 + ((k>>2)&1)
__device__ __forceinline__ size_t idxB(int K, int N, int Ck) {
    return ((size_t)((N >> 3) * (Ck >> 3) + (K >> 3))) * 64
         + (size_t)(((N & 7) * 4 + (K & 3)) * 2 + ((K >> 2) & 1));
}
__device__ __forceinline__ void wsplitA(float* H, float* L, int M, int K, int Ck, float v) {
    float hi = to_tf32(v);
    float lo = to_tf32(v - hi);
    size_t i = idxA(M, K, Ck);
    H[i] = hi; L[i] = lo;
}
__device__ __forceinline__ void wsplitB(float* H, float* L, int K, int N, int Ck, float v) {
    float hi = to_tf32(v);
    float lo = to_tf32(v - hi);
    size_t i = idxB(K, N, Ck);
    H[i] = hi; L[i] = lo;
}

__device__ __forceinline__ void cpasync16(uint32_t dst, const float* src) {
    asm volatile("cp.async.cg.shared.global [%0], [%1], 16;" :: "r"(dst), "l"(src));
}

// ===========================================================================
// MMA core: acc[4][4][4] += A[128 x 32*nchunks] * B^T  (3-pass tf32 split)
// A operands in A-layout (h/l), B operands in B-layout (h/l).
// 256 threads; warps: wm = (wid&1) in {0,1} (m 64-halves), wn = wid>>1 (n 32-quarters)
// smem: 2 buffers x [Ah 16KB | Al 16KB | Bh 16KB | Bl 16KB] = 128KB dynamic.
// ===========================================================================
__device__ __forceinline__ void mma_core(
    const float* __restrict__ Ah, const float* __restrict__ Al, int row0A, int aKt,
    const float* __restrict__ Bh, const float* __restrict__ Bl, int col0B, int bKt,
    int nchunks, float acc[4][4][4])
{
    extern __shared__ float smem[];
    const int tid  = threadIdx.x;
    const int lane = tid & 31;
    const int wm   = (tid >> 5) & 1;
    const int wn   = tid >> 6;
    const uint32_t sb_u32 = smem_to_u32(smem);

    const int aRB0 = (row0A >> 4) * aKt;
    const int bRB0 = (col0B >> 3) * bKt;

    // ---- stage one chunk via cp.async ----
    auto copy_chunk = [&](int chunk) {
        const uint32_t sbase = sb_u32 + (uint32_t)(chunk & 1) * 65536u;
        const int aRB = aRB0 + chunk * 4;
        const int bRB = bRB0 + chunk * 4;
#pragma unroll
        for (int c = tid; c < 1024; c += 256) {          // A: 32 regions x 512B
            int reg = c >> 5, inner = (c & 31) << 2;
            size_t off = (size_t)(aRB + (reg >> 2) * aKt + (reg & 3)) * 128 + inner;
            uint32_t d = sbase + (uint32_t)((reg * 128 + inner) << 2);
            cpasync16(d,          Ah + off);
            cpasync16(d + 16384u, Al + off);
        }
#pragma unroll
        for (int c = tid; c < 1024; c += 256) {          // B: 64 regions x 256B
            int reg = c >> 4, inner = (c & 15) << 2;
            size_t off = (size_t)(bRB + (reg >> 2) * bKt + (reg & 3)) * 64 + inner;
            uint32_t d = sbase + 32768u + (uint32_t)((reg * 64 + inner) << 2);
            cpasync16(d,          Bh + off);
            cpasync16(d + 16384u, Bl + off);
        }
        asm volatile("cp.async.commit_group;");
    };

    copy_chunk(0);
    for (int t = 0; t < nchunks; t++) {
        if (t + 1 < nchunks) {
            copy_chunk(t + 1);
            asm volatile("cp.async.wait_group 1;");
        } else {
            asm volatile("cp.async.wait_group 0;");
        }
        __syncthreads();

        const float* sb  = smem + (size_t)(t & 1) * 16384;
        const uint4* pAh = (const uint4*)sb;
        const uint4* pAl = (const uint4*)(sb + 4096);
        const uint2* pBh = (const uint2*)(sb + 8192);
        const uint2* pBl = (const uint2*)(sb + 12288);

#pragma unroll
        for (int ki = 0; ki < 4; ki++) {
            uint4 fAh[4]; uint2 fBh[4];
#pragma unroll
            for (int f = 0; f < 4; f++)
                fAh[f] = pAh[((wm * 4 + f) * 4 + ki) * 32 + lane];
#pragma unroll
            for (int g = 0; g < 4; g++)
                fBh[g] = pBh[((wn * 4 + g) * 4 + ki) * 32 + lane];
            // pass hh
#pragma unroll
            for (int f = 0; f < 4; f++)
#pragma unroll
                for (int g = 0; g < 4; g++) mma8(acc[f][g], fAh[f], fBh[g]);
            // pass lh (Al * Bh)
            {
                uint4 fAl[4];
#pragma unroll
                for (int f = 0; f < 4; f++)
                    fAl[f] = pAl[((wm * 4 + f) * 4 + ki) * 32 + lane];
#pragma unroll
                for (int f = 0; f < 4; f++)
#pragma unroll
                    for (int g = 0; g < 4; g++) mma8(acc[f][g], fAl[f], fBh[g]);
            }
            // pass hl (Ah * Bl)
            {
                uint2 fBl[4];
#pragma unroll
                for (int g = 0; g < 4; g++)
                    fBl[g] = pBl[((wn * 4 + g) * 4 + ki) * 32 + lane];
#pragma unroll
                for (int f = 0; f < 4; f++)
#pragma unroll
                    for (int g = 0; g < 4; g++) mma8(acc[f][g], fAh[f], fBl[g]);
            }
        }
        __syncthreads();
    }
}

// Accumulator coordinates: m = wm*64 + f*16 + (lane>>2) (+8 for regs 2,3),
//                          n = wn*32 + g*8 + (lane&3)*2 (+1 for regs 1,3)

// ===========================================================================
// Kernel: split X -> A-layout h/l
// ===========================================================================
__global__ void __launch_bounds__(256) k_splitX(const float* __restrict__ X)
{
    int i = blockIdx.x * 256 + threadIdx.x;      // over (BB*TT*DD)/4 float4s
    int m  = i >> 8;                             // DD/4 = 256 float4 per row
    int d0 = (i & 255) << 2;
    float4 v = *(const float4*)(X + (size_t)m * DD + d0);
#pragma unroll
    for (int e = 0; e < 4; e++)
        wsplitA(g_Xh, g_Xl, m, d0 + e, DD, (&v.x)[e]);
}

// ===========================================================================
// Kernel: split W (3 matrices) -> B-layout h/l  (k = d_in, n = d_out)
// ===========================================================================
__global__ void __launch_bounds__(256) k_splitW(
    const float* __restrict__ Wq, const float* __restrict__ Wk,
    const float* __restrict__ Wv)
{
    int z = blockIdx.z;
    const float* W = (z == 0) ? Wq : (z == 1) ? Wk : Wv;
    float* H = g_Wh + (size_t)z * DD * DD;
    float* L = g_Wl + (size_t)z * DD * DD;
    int i = blockIdx.x * 256 + threadIdx.x;      // over (DD*DD)/4
    int r  = i >> 8;
    int c0 = (i & 255) << 2;
    float4 v = *(const float4*)(W + (size_t)r * DD + c0);
#pragma unroll
    for (int e = 0; e < 4; e++)
        wsplitB(H, L, r, c0 + e, DD, (&v.x)[e]);
}

// ===========================================================================
// Kernel: QKV projection. grid (DD/128, B*T/128, 3)
//   C = X * W[z]; epilogue writes split arrays in the layout each consumer needs.
// ===========================================================================
__global__ void __launch_bounds__(256) k_proj()
{
    const int z    = blockIdx.z;
    const int row0 = blockIdx.y * 128;           // global row over B*T
    const int col0 = blockIdx.x * 128;

    float acc[4][4][4];
#pragma unroll
    for (int f = 0; f < 4; f++)
#pragma unroll
        for (int g = 0; g < 4; g++)
#pragma unroll
            for (int r = 0; r < 4; r++) acc[f][g][r] = 0.0f;

    mma_core(g_Xh, g_Xl, row0, DD >> 3,
             g_Wh + (size_t)z * DD * DD, g_Wl + (size_t)z * DD * DD, col0, DD >> 3,
             DD >> 5, acc);

    const int lane = threadIdx.x & 31;
    const int wm   = (threadIdx.x >> 5) & 1;
    const int wn   = threadIdx.x >> 6;
    const int mb   = wm * 64 + (lane >> 2);
    const int nb   = wn * 32 + (lane & 3) * 2;

#pragma unroll
    for (int f = 0; f < 4; f++) {
#pragma unroll
        for (int g = 0; g < 4; g++) {
#pragma unroll
            for (int r = 0; r < 4; r++) {
                int M = row0 + mb + f * 16 + ((r >> 1) << 3);
                int N = col0 + nb + g * 8 + (r & 1);
                float v = acc[f][g][r];
                if (z == 0) {
                    wsplitA(g_Qh, g_Ql, M, N, DD, v);
                } else if (z == 1) {
                    wsplitB(g_Kh, g_Kl, N, M, DD, v);   // k = d, n = s(global)
                } else {
                    int b  = M >> 11;
                    int sl = M & (TT - 1);
                    wsplitB(g_Vh + (size_t)b * TT * DD,
                            g_Vl + (size_t)b * TT * DD, sl, N, TT, v); // k = s, n = d
                }
            }
        }
    }
}

// ===========================================================================
// Kernel: scores S = (Q K^T)/32, lower-triangular tiles only. grid (16,16,4)
// ===========================================================================
__global__ void __launch_bounds__(256) k_scores()
{
    if (blockIdx.x > blockIdx.y) return;
    const int b    = blockIdx.z;
    const int row0 = b * TT + blockIdx.y * 128;  // global row (Q)
    const int col0 = b * TT + blockIdx.x * 128;  // global row (K)

    float acc[4][4][4];
#pragma unroll
    for (int f = 0; f < 4; f++)
#pragma unroll
        for (int g = 0; g < 4; g++)
#pragma unroll
            for (int r = 0; r < 4; r++) acc[f][g][r] = 0.0f;

    mma_core(g_Qh, g_Ql, row0, DD >> 3,
             g_Kh, g_Kl, col0, DD >> 3, DD >> 5, acc);

    float* C = g_S + (size_t)b * TT * TT;
    const int lane = threadIdx.x & 31;
    const int wm   = (threadIdx.x >> 5) & 1;
    const int wn   = threadIdx.x >> 6;
    const int mb   = blockIdx.y * 128 + wm * 64 + (lane >> 2);
    const int nb   = blockIdx.x * 128 + wn * 32 + (lane & 3) * 2;

#pragma unroll
    for (int f = 0; f < 4; f++)
#pragma unroll
        for (int g = 0; g < 4; g++)
#pragma unroll
            for (int r = 0; r < 4; r++) {
                int M = mb + f * 16 + ((r >> 1) << 3);
                int N = nb + g * 8 + (r & 1);
                C[(size_t)M * TT + N] = acc[f][g][r] * 0.03125f;
            }
}

// ===========================================================================
// Kernel: causal softmax; writes split S (A-layout) for the PV GEMM.
// ===========================================================================
__global__ void __launch_bounds__(256) k_softmax()
{
    const int row = blockIdx.x;                  // global over B*T
    const int i   = row & (TT - 1);
    const float* s = g_S + (size_t)row * TT;
    const int L = i + 1;
    const int tid = threadIdx.x;
    __shared__ float red[256];

    float m = -CUDART_INF_F;
    for (int j = tid; j < L; j += 256) m = fmaxf(m, s[j]);
    red[tid] = m;
    __syncthreads();
    for (int w = 128; w > 0; w >>= 1) {
        if (tid < w) red[tid] = fmaxf(red[tid], red[tid + w]);
        __syncthreads();
    }
    m = red[0];
    __syncthreads();

    float sum = 0.0f;
    for (int j = tid; j < L; j += 256) sum += __expf(s[j] - m);
    red[tid] = sum;
    __syncthreads();
    for (int w = 128; w > 0; w >>= 1) {
        if (tid < w) red[tid] += red[tid + w];
        __syncthreads();
    }
    const float inv = 1.0f / red[0];

    for (int j4 = tid * 4; j4 < TT; j4 += 1024) {
#pragma unroll
        for (int e = 0; e < 4; e++) {
            int j = j4 + e;
            float w = (j < L) ? __expf(s[j] - m) * inv : 0.0f;
            wsplitA(g_Sh, g_Sl, row, j, TT, w);
        }
    }
}

// ===========================================================================
// Kernel: O = S_w * V, k clamped to causal extent. grid (DD/128, 16, 4)
// ===========================================================================
__global__ void __launch_bounds__(256) k_pv(float* __restrict__ out)
{
    const int b    = blockIdx.z;
    const int row0 = b * TT + blockIdx.y * 128;  // global row (S)
    const int col0 = blockIdx.x * 128;           // d (V is per-batch B-layout)

    float acc[4][4][4];
#pragma unroll
    for (int f = 0; f < 4; f++)
#pragma unroll
        for (int g = 0; g < 4; g++)
#pragma unroll
            for (int r = 0; r < 4; r++) acc[f][g][r] = 0.0f;

    mma_core(g_Sh, g_Sl, row0, TT >> 3,
             g_Vh + (size_t)b * TT * DD, g_Vl + (size_t)b * TT * DD, col0, TT >> 3,
             ((int)blockIdx.y + 1) * 4, acc);

    float* C = out + (size_t)b * TT * DD;
    const int lane = threadIdx.x & 31;
    const int wm   = (threadIdx.x >> 5) & 1;
    const int wn   = threadIdx.x >> 6;
    const int mb   = blockIdx.y * 128 + wm * 64 + (lane >> 2);
    const int nb   = col0 + wn * 32 + (lane & 3) * 2;

#pragma unroll
    for (int f = 0; f < 4; f++)
#pragma unroll
        for (int g = 0; g < 4; g++)
#pragma unroll
            for (int r = 0; r < 4; r++) {
                int M = mb + f * 16 + ((r >> 1) << 3);
                int N = nb + g * 8 + (r & 1);
                C[(size_t)M * DD + N] = acc[f][g][r];
            }
}

// ===========================================================================
extern "C" void kernel_launch(void* const* d_in, const int* in_sizes, int n_in,
                              void* d_out, int out_size)
{
    const float* X  = (const float*)d_in[0];
    const float* Wq = (const float*)d_in[1];
    const float* Wk = (const float*)d_in[2];
    const float* Wv = (const float*)d_in[3];
    float* out = (float*)d_out;

    const int SMEMB = 131072;   // 2 x 64KB buffers
    cudaFuncSetAttribute(k_proj,   cudaFuncAttributeMaxDynamicSharedMemorySize, SMEMB);
    cudaFuncSetAttribute(k_scores, cudaFuncAttributeMaxDynamicSharedMemorySize, SMEMB);
    cudaFuncSetAttribute(k_pv,     cudaFuncAttributeMaxDynamicSharedMemorySize, SMEMB);

    k_splitX <<<(BB * TT * DD) / 1024, 256>>>(X);
    k_splitW <<<dim3((DD * DD) / 1024, 1, 3), 256>>>(Wq, Wk, Wv);
    k_proj   <<<dim3(DD / 128, (BB * TT) / 128, 3), 256, SMEMB>>>();
    k_scores <<<dim3(TT / 128, TT / 128, BB), 256, SMEMB>>>();
    k_softmax<<<BB * TT, 256>>>();
    k_pv     <<<dim3(DD / 128, TT / 128, BB), 256, SMEMB>>>(out);
}

// round 6
// speedup vs baseline: 3.0399x; 3.0399x over previous
#include <cuda_runtime.h>
#include <cuda_fp16.h>
#include <math_constants.h>
#include <cstdint>

#define BB 4
#define TT 2048
#define DD 1024

// ============ scratch: fp16 hi/lo split arrays in mma fragment order =======
// A-layout region (m16 x k16): 32 lanes x 4 regs x half2 = 512 B (128 u32)
// B-layout region (n8  x k16): 32 lanes x 2 regs x half2 = 256 B (64 u32)
__device__ __half2 g_Xh[(size_t)BB * TT * DD / 2];
__device__ __half2 g_Xl[(size_t)BB * TT * DD / 2];
__device__ __half2 g_Wh[(size_t)3 * DD * DD / 2];
__device__ __half2 g_Wl[(size_t)3 * DD * DD / 2];
__device__ __half2 g_Qh[(size_t)BB * TT * DD / 2];
__device__ __half2 g_Ql[(size_t)BB * TT * DD / 2];
__device__ __half2 g_Kh[(size_t)BB * TT * DD / 2];
__device__ __half2 g_Kl[(size_t)BB * TT * DD / 2];
__device__ __half2 g_Vh[(size_t)BB * TT * DD / 2];
__device__ __half2 g_Vl[(size_t)BB * TT * DD / 2];
__device__ float   g_S [(size_t)BB * TT * TT];
__device__ __half2 g_Sh[(size_t)BB * TT * TT / 2];
__device__ __half2 g_Sl[(size_t)BB * TT * TT / 2];

// ============================ helpers ======================================
__device__ __forceinline__ uint32_t smem_to_u32(const void* p) {
    uint32_t a;
    asm("{ .reg .u64 t; cvta.to.shared.u64 t, %1; cvt.u32.u64 %0, t; }"
        : "=r"(a) : "l"(p));
    return a;
}

// fp16 mma m16n8k16, fp32 accumulate (baseline sm_80 PTX)
__device__ __forceinline__ void mma16(float* d, uint4 a, uint2 b) {
    asm volatile(
        "mma.sync.aligned.m16n8k16.row.col.f32.f16.f16.f32 "
        "{%0,%1,%2,%3}, {%4,%5,%6,%7}, {%8,%9}, {%0,%1,%2,%3};"
        : "+f"(d[0]), "+f"(d[1]), "+f"(d[2]), "+f"(d[3])
        : "r"(a.x), "r"(a.y), "r"(a.z), "r"(a.w), "r"(b.x), "r"(b.y));
}

// u32 (=half2) index inside A-layout / B-layout arrays (k must be even).
__device__ __forceinline__ size_t idxA32(int m, int k, int Kt) {
    return ((size_t)((m >> 4) * (Kt >> 4) + (k >> 4))) * 128
         + (size_t)((((m & 7) * 4 + ((k & 7) >> 1)) * 4)
                    + ((m >> 3) & 1) + (((k >> 3) & 1) << 1));
}
__device__ __forceinline__ size_t idxB32(int k, int n, int Kt) {
    return ((size_t)((n >> 3) * (Kt >> 4) + (k >> 4))) * 64
         + (size_t)((((n & 7) * 4 + ((k & 7) >> 1)) * 2) + ((k >> 3) & 1));
}

__device__ __forceinline__ void split1(float x, __half& h, __half& l) {
    h = __float2half_rn(x);
    l = __float2half_rn(x - __half2float(h));
}
__device__ __forceinline__ void wsplitA_pair(
    __half2* H, __half2* L, int m, int k, int Kt, float x0, float x1)
{
    __half h0, l0, h1, l1;
    split1(x0, h0, l0); split1(x1, h1, l1);
    size_t i = idxA32(m, k, Kt);
    H[i] = __halves2half2(h0, h1);
    L[i] = __halves2half2(l0, l1);
}
__device__ __forceinline__ void wsplitB_pair(
    __half2* H, __half2* L, int k, int n, int Kt, float x0, float x1)
{
    __half h0, l0, h1, l1;
    split1(x0, h0, l0); split1(x1, h1, l1);
    size_t i = idxB32(k, n, Kt);
    H[i] = __halves2half2(h0, h1);
    L[i] = __halves2half2(l0, l1);
}
// single-half B-layout write (odd strides along k): for V epilogue
__device__ __forceinline__ void wsplitB_half(
    __half2* H, __half2* L, int k, int n, int Kt, float x)
{
    __half h, l;
    split1(x, h, l);
    size_t i = idxB32(k, n, Kt) * 2 + (size_t)(k & 1);
    ((__half*)H)[i] = h;
    ((__half*)L)[i] = l;
}

__device__ __forceinline__ void cpasync16(uint32_t dst, const void* src) {
    asm volatile("cp.async.cg.shared.global [%0], [%1], 16;" :: "r"(dst), "l"(src));
}

// ===========================================================================
// MMA core: acc[4][4][4] += A[128 x 32*nchunks] * B^T, fp16 3-pass (hh,lh,hl)
// smem/buffer: [Ah 8K][Al 8K][Bh 8K][Bl 8K] = 32KB; 2 buffers = 64KB.
// 256 threads: wm=(wid&1) m-64-half, wn=wid>>2... (wn = wid>>1) n-32-quarter.
// ===========================================================================
__device__ __forceinline__ void mma_core(
    const __half2* __restrict__ Ah, const __half2* __restrict__ Al,
    int row0A, int aKt,
    const __half2* __restrict__ Bh, const __half2* __restrict__ Bl,
    int col0B, int bKt,
    int nchunks, float acc[4][4][4])
{
    extern __shared__ char smem[];
    const int tid  = threadIdx.x;
    const int lane = tid & 31;
    const int wm   = (tid >> 5) & 1;
    const int wn   = tid >> 6;
    const uint32_t sb_u32 = smem_to_u32(smem);

    const int aRB0 = (row0A >> 4) * aKt;   // in k16-region units
    const int bRB0 = (col0B >> 3) * bKt;

    auto copy_chunk = [&](int chunk) {
        const uint32_t sbase = sb_u32 + (uint32_t)(chunk & 1) * 32768u;
        // A: 16 regions (8 m-tiles x 2 kregs) x 512B = 8KB per array
        for (int c = tid; c < 512; c += 256) {
            int rr = c >> 5;                       // region 0..15
            size_t off = (size_t)(aRB0 + (rr >> 1) * aKt + chunk * 2 + (rr & 1)) * 128
                       + (size_t)((c & 31) << 2);
            uint32_t d = sbase + (uint32_t)(c << 4);
            cpasync16(d,         Ah + off);
            cpasync16(d + 8192u, Al + off);
        }
        // B: 32 regions (16 n-tiles x 2 kregs) x 256B = 8KB per array
        for (int c = tid; c < 512; c += 256) {
            int rr = c >> 4;                       // region 0..31
            size_t off = (size_t)(bRB0 + (rr >> 1) * bKt + chunk * 2 + (rr & 1)) * 64
                       + (size_t)((c & 15) << 2);
            uint32_t d = sbase + 16384u + (uint32_t)(c << 4);
            cpasync16(d,         Bh + off);
            cpasync16(d + 8192u, Bl + off);
        }
        asm volatile("cp.async.commit_group;");
    };

    copy_chunk(0);
    for (int t = 0; t < nchunks; t++) {
        if (t + 1 < nchunks) {
            copy_chunk(t + 1);
            asm volatile("cp.async.wait_group 1;");
        } else {
            asm volatile("cp.async.wait_group 0;");
        }
        __syncthreads();

        const char* sb = smem + (size_t)(t & 1) * 32768;
        const uint4* pAh = (const uint4*)sb;
        const uint4* pAl = (const uint4*)(sb + 8192);
        const uint2* pBh = (const uint2*)(sb + 16384);
        const uint2* pBl = (const uint2*)(sb + 24576);

#pragma unroll
        for (int ki = 0; ki < 2; ki++) {
            uint4 fAh[4]; uint2 fBh[4];
#pragma unroll
            for (int f = 0; f < 4; f++)
                fAh[f] = pAh[((wm * 4 + f) * 2 + ki) * 32 + lane];
#pragma unroll
            for (int g = 0; g < 4; g++)
                fBh[g] = pBh[((wn * 4 + g) * 2 + ki) * 32 + lane];
            // hh
#pragma unroll
            for (int f = 0; f < 4; f++)
#pragma unroll
                for (int g = 0; g < 4; g++) mma16(acc[f][g], fAh[f], fBh[g]);
            // lh
            {
                uint4 fAl[4];
#pragma unroll
                for (int f = 0; f < 4; f++)
                    fAl[f] = pAl[((wm * 4 + f) * 2 + ki) * 32 + lane];
#pragma unroll
                for (int f = 0; f < 4; f++)
#pragma unroll
                    for (int g = 0; g < 4; g++) mma16(acc[f][g], fAl[f], fBh[g]);
            }
            // hl
            {
                uint2 fBl[4];
#pragma unroll
                for (int g = 0; g < 4; g++)
                    fBl[g] = pBl[((wn * 4 + g) * 2 + ki) * 32 + lane];
#pragma unroll
                for (int f = 0; f < 4; f++)
#pragma unroll
                    for (int g = 0; g < 4; g++) mma16(acc[f][g], fAh[f], fBl[g]);
            }
        }
        __syncthreads();
    }
}
// acc coords: m = wm*64 + f*16 + (lane>>2) + 8*(r>>1); n = wn*32 + g*8 + (lane&3)*2 + (r&1)

// ===========================================================================
__global__ void __launch_bounds__(256) k_splitX(const float* __restrict__ X)
{
    int i = blockIdx.x * 256 + threadIdx.x;      // over (BB*TT*DD)/4 float4s
    int m  = i >> 8;
    int d0 = (i & 255) << 2;
    float4 v = *(const float4*)(X + (size_t)m * DD + d0);
    wsplitA_pair(g_Xh, g_Xl, m, d0,     DD, v.x, v.y);
    wsplitA_pair(g_Xh, g_Xl, m, d0 + 2, DD, v.z, v.w);
}

__global__ void __launch_bounds__(256) k_splitW(
    const float* __restrict__ Wq, const float* __restrict__ Wk,
    const float* __restrict__ Wv)
{
    int z = blockIdx.z;
    const float* W = (z == 0) ? Wq : (z == 1) ? Wk : Wv;
    __half2* H = g_Wh + (size_t)z * DD * DD / 2;
    __half2* L = g_Wl + (size_t)z * DD * DD / 2;
    int i = blockIdx.x * 256 + threadIdx.x;      // over DD*DD/2 (k-pairs)
    int r2 = (i >> 10) << 1;                     // DD columns per row
    int c  = i & 1023;
    float x0 = W[(size_t)r2 * DD + c];
    float x1 = W[(size_t)(r2 + 1) * DD + c];
    wsplitB_pair(H, L, r2, c, DD, x0, x1);       // k = d_in rows, n = d_out col
}

// ===========================================================================
// QKV projection. grid (DD/128, B*T/128, 3).
// ===========================================================================
__global__ void __launch_bounds__(256, 2) k_proj()
{
    const int z    = blockIdx.z;
    const int row0 = blockIdx.y * 128;
    const int col0 = blockIdx.x * 128;

    float acc[4][4][4];
#pragma unroll
    for (int f = 0; f < 4; f++)
#pragma unroll
        for (int g = 0; g < 4; g++)
#pragma unroll
            for (int r = 0; r < 4; r++) acc[f][g][r] = 0.0f;

    mma_core(g_Xh, g_Xl, row0, DD >> 4,
             g_Wh + (size_t)z * DD * DD / 2, g_Wl + (size_t)z * DD * DD / 2,
             col0, DD >> 4, DD >> 5, acc);

    const int lane = threadIdx.x & 31;
    const int wm   = (threadIdx.x >> 5) & 1;
    const int wn   = threadIdx.x >> 6;
    const int mb   = row0 + wm * 64 + (lane >> 2);
    const int nb   = col0 + wn * 32 + (lane & 3) * 2;   // even

#pragma unroll
    for (int f = 0; f < 4; f++) {
#pragma unroll
        for (int g = 0; g < 4; g++) {
            int M0 = mb + f * 16;
            int N  = nb + g * 8;
            float a0 = acc[f][g][0], a1 = acc[f][g][1];
            float a2 = acc[f][g][2], a3 = acc[f][g][3];
            if (z == 0) {
                wsplitA_pair(g_Qh, g_Ql, M0,     N, DD, a0, a1);
                wsplitA_pair(g_Qh, g_Ql, M0 + 8, N, DD, a2, a3);
            } else if (z == 1) {
                wsplitB_pair(g_Kh, g_Kl, N, M0,     DD, a0, a1);
                wsplitB_pair(g_Kh, g_Kl, N, M0 + 8, DD, a2, a3);
            } else {
#pragma unroll
                for (int r = 0; r < 4; r++) {
                    int M  = M0 + ((r >> 1) << 3);
                    int b  = M >> 11;
                    int sl = M & (TT - 1);
                    float v = acc[f][g][r];
                    wsplitB_half(g_Vh + (size_t)b * TT * DD / 2,
                                 g_Vl + (size_t)b * TT * DD / 2,
                                 sl, N + (r & 1), TT, v);
                }
            }
        }
    }
}

// ===========================================================================
// Scores S = (Q K^T)/32, lower-triangular tiles. grid (16,16,4)
// ===========================================================================
__global__ void __launch_bounds__(256, 2) k_scores()
{
    if (blockIdx.x > blockIdx.y) return;
    const int b    = blockIdx.z;
    const int row0 = b * TT + blockIdx.y * 128;
    const int col0 = b * TT + blockIdx.x * 128;

    float acc[4][4][4];
#pragma unroll
    for (int f = 0; f < 4; f++)
#pragma unroll
        for (int g = 0; g < 4; g++)
#pragma unroll
            for (int r = 0; r < 4; r++) acc[f][g][r] = 0.0f;

    mma_core(g_Qh, g_Ql, row0, DD >> 4,
             g_Kh, g_Kl, col0, DD >> 4, DD >> 5, acc);

    float* C = g_S + (size_t)b * TT * TT;
    const int lane = threadIdx.x & 31;
    const int wm   = (threadIdx.x >> 5) & 1;
    const int wn   = threadIdx.x >> 6;
    const int mb   = blockIdx.y * 128 + wm * 64 + (lane >> 2);
    const int nb   = blockIdx.x * 128 + wn * 32 + (lane & 3) * 2;

#pragma unroll
    for (int f = 0; f < 4; f++)
#pragma unroll
        for (int g = 0; g < 4; g++)
#pragma unroll
            for (int r = 0; r < 4; r++) {
                int M = mb + f * 16 + ((r >> 1) << 3);
                int N = nb + g * 8 + (r & 1);
                C[(size_t)M * TT + N] = acc[f][g][r] * 0.03125f;
            }
}

// ===========================================================================
// Causal softmax; writes split weights (A-layout) for PV.
// ===========================================================================
__global__ void __launch_bounds__(256) k_softmax()
{
    const int row = blockIdx.x;
    const int i   = row & (TT - 1);
    const float* s = g_S + (size_t)row * TT;
    const int L = i + 1;
    const int tid = threadIdx.x;
    __shared__ float red[256];

    float m = -CUDART_INF_F;
    for (int j = tid; j < L; j += 256) m = fmaxf(m, s[j]);
    red[tid] = m;
    __syncthreads();
    for (int w = 128; w > 0; w >>= 1) {
        if (tid < w) red[tid] = fmaxf(red[tid], red[tid + w]);
        __syncthreads();
    }
    m = red[0];
    __syncthreads();

    float sum = 0.0f;
    for (int j = tid; j < L; j += 256) sum += __expf(s[j] - m);
    red[tid] = sum;
    __syncthreads();
    for (int w = 128; w > 0; w >>= 1) {
        if (tid < w) red[tid] += red[tid + w];
        __syncthreads();
    }
    const float inv = 1.0f / red[0];

    for (int j4 = tid * 4; j4 < TT; j4 += 1024) {
        float w[4];
#pragma unroll
        for (int e = 0; e < 4; e++) {
            int j = j4 + e;
            w[e] = (j < L) ? __expf(s[j] - m) * inv : 0.0f;
        }
        wsplitA_pair(g_Sh, g_Sl, row, j4,     TT, w[0], w[1]);
        wsplitA_pair(g_Sh, g_Sl, row, j4 + 2, TT, w[2], w[3]);
    }
}

// ===========================================================================
// O = S_w * V, k clamped to causal extent. grid (DD/128, 16, 4)
// ===========================================================================
__global__ void __launch_bounds__(256, 2) k_pv(float* __restrict__ out)
{
    const int b    = blockIdx.z;
    const int row0 = b * TT + blockIdx.y * 128;
    const int col0 = blockIdx.x * 128;

    float acc[4][4][4];
#pragma unroll
    for (int f = 0; f < 4; f++)
#pragma unroll
        for (int g = 0; g < 4; g++)
#pragma unroll
            for (int r = 0; r < 4; r++) acc[f][g][r] = 0.0f;

    mma_core(g_Sh, g_Sl, row0, TT >> 4,
             g_Vh + (size_t)b * TT * DD / 2, g_Vl + (size_t)b * TT * DD / 2,
             col0, TT >> 4, ((int)blockIdx.y + 1) * 4, acc);

    float* C = out + (size_t)b * TT * DD;
    const int lane = threadIdx.x & 31;
    const int wm   = (threadIdx.x >> 5) & 1;
    const int wn   = threadIdx.x >> 6;
    const int mb   = blockIdx.y * 128 + wm * 64 + (lane >> 2);
    const int nb   = col0 + wn * 32 + (lane & 3) * 2;

#pragma unroll
    for (int f = 0; f < 4; f++)
#pragma unroll
        for (int g = 0; g < 4; g++)
#pragma unroll
            for (int r = 0; r < 4; r++) {
                int M = mb + f * 16 + ((r >> 1) << 3);
                int N = nb + g * 8 + (r & 1);
                C[(size_t)M * DD + N] = acc[f][g][r];
            }
}

// ===========================================================================
extern "C" void kernel_launch(void* const* d_in, const int* in_sizes, int n_in,
                              void* d_out, int out_size)
{
    const float* X  = (const float*)d_in[0];
    const float* Wq = (const float*)d_in[1];
    const float* Wk = (const float*)d_in[2];
    const float* Wv = (const float*)d_in[3];
    float* out = (float*)d_out;

    const int SMEMB = 65536;   // 2 x 32KB buffers
    cudaFuncSetAttribute(k_proj,   cudaFuncAttributeMaxDynamicSharedMemorySize, SMEMB);
    cudaFuncSetAttribute(k_scores, cudaFuncAttributeMaxDynamicSharedMemorySize, SMEMB);
    cudaFuncSetAttribute(k_pv,     cudaFuncAttributeMaxDynamicSharedMemorySize, SMEMB);

    k_splitX <<<(BB * TT * DD) / 1024, 256>>>(X);
    k_splitW <<<dim3((DD * DD) / 512, 1, 3), 256>>>(Wq, Wk, Wv);
    k_proj   <<<dim3(DD / 128, (BB * TT) / 128, 3), 256, SMEMB>>>();
    k_scores <<<dim3(TT / 128, TT / 128, BB), 256, SMEMB>>>();
    k_softmax<<<BB * TT, 256>>>();
    k_pv     <<<dim3(DD / 128, TT / 128, BB), 256, SMEMB>>>(out);
}

// round 7
// speedup vs baseline: 3.2646x; 1.0739x over previous
#include <cuda_runtime.h>
#include <cuda_fp16.h>
#include <math_constants.h>
#include <cstdint>

#define BB 4
#define TT 2048
#define DD 1024

// ============ scratch: fp16 hi/lo split arrays in mma fragment order =======
__device__ __half2 g_Xh[(size_t)BB * TT * DD / 2];
__device__ __half2 g_Xl[(size_t)BB * TT * DD / 2];
__device__ __half2 g_Wh[(size_t)3 * DD * DD / 2];
__device__ __half2 g_Wl[(size_t)3 * DD * DD / 2];
__device__ __half2 g_Qh[(size_t)BB * TT * DD / 2];
__device__ __half2 g_Ql[(size_t)BB * TT * DD / 2];
__device__ __half2 g_Kh[(size_t)BB * TT * DD / 2];
__device__ __half2 g_Kl[(size_t)BB * TT * DD / 2];
__device__ __half2 g_Vh[(size_t)BB * TT * DD / 2];
__device__ __half2 g_Vl[(size_t)BB * TT * DD / 2];
__device__ float   g_S [(size_t)BB * TT * TT];
__device__ __half2 g_Sh[(size_t)BB * TT * TT / 2];
__device__ __half2 g_Sl[(size_t)BB * TT * TT / 2];

// ============================ helpers ======================================
__device__ __forceinline__ uint32_t smem_to_u32(const void* p) {
    uint32_t a;
    asm("{ .reg .u64 t; cvta.to.shared.u64 t, %1; cvt.u32.u64 %0, t; }"
        : "=r"(a) : "l"(p));
    return a;
}

__device__ __forceinline__ void mma16(float* d, uint4 a, uint2 b) {
    asm volatile(
        "mma.sync.aligned.m16n8k16.row.col.f32.f16.f16.f32 "
        "{%0,%1,%2,%3}, {%4,%5,%6,%7}, {%8,%9}, {%0,%1,%2,%3};"
        : "+f"(d[0]), "+f"(d[1]), "+f"(d[2]), "+f"(d[3])
        : "r"(a.x), "r"(a.y), "r"(a.z), "r"(a.w), "r"(b.x), "r"(b.y));
}

__device__ __forceinline__ size_t idxA32(int m, int k, int Kt) {
    return ((size_t)((m >> 4) * (Kt >> 4) + (k >> 4))) * 128
         + (size_t)((((m & 7) * 4 + ((k & 7) >> 1)) * 4)
                    + ((m >> 3) & 1) + (((k >> 3) & 1) << 1));
}
__device__ __forceinline__ size_t idxB32(int k, int n, int Kt) {
    return ((size_t)((n >> 3) * (Kt >> 4) + (k >> 4))) * 64
         + (size_t)((((n & 7) * 4 + ((k & 7) >> 1)) * 2) + ((k >> 3) & 1));
}

__device__ __forceinline__ void split1(float x, __half& h, __half& l) {
    h = __float2half_rn(x);
    l = __float2half_rn(x - __half2float(h));
}
__device__ __forceinline__ void wsplitA_pair(
    __half2* H, __half2* L, int m, int k, int Kt, float x0, float x1)
{
    __half h0, l0, h1, l1;
    split1(x0, h0, l0); split1(x1, h1, l1);
    size_t i = idxA32(m, k, Kt);
    H[i] = __halves2half2(h0, h1);
    L[i] = __halves2half2(l0, l1);
}
__device__ __forceinline__ void wsplitB_pair(
    __half2* H, __half2* L, int k, int n, int Kt, float x0, float x1)
{
    __half h0, l0, h1, l1;
    split1(x0, h0, l0); split1(x1, h1, l1);
    size_t i = idxB32(k, n, Kt);
    H[i] = __halves2half2(h0, h1);
    L[i] = __halves2half2(l0, l1);
}
__device__ __forceinline__ void wsplitB_half(
    __half2* H, __half2* L, int k, int n, int Kt, float x)
{
    __half h, l;
    split1(x, h, l);
    size_t i = idxB32(k, n, Kt) * 2 + (size_t)(k & 1);
    ((__half*)H)[i] = h;
    ((__half*)L)[i] = l;
}

__device__ __forceinline__ void cpasync16(uint32_t dst, const void* src) {
    asm volatile("cp.async.cg.shared.global [%0], [%1], 16;" :: "r"(dst), "l"(src));
}

// ===========================================================================
// MMA core: acc[4][4][4] += A[128 x 32*nchunks] * B^T, fp16 split passes.
// NPASS = 3: hh + lh + hl; NPASS = 2: hh + lh.
// 3-stage cp.async pipeline, ONE __syncthreads per chunk.
// smem/buffer 32KB: [Ah 8K][Al 8K][Bh 8K][Bl 8K]; 3 buffers = 96KB.
// ===========================================================================
template<int NPASS>
__device__ __forceinline__ void mma_core(
    const __half2* __restrict__ Ah, const __half2* __restrict__ Al,
    int row0A, int aKt,
    const __half2* __restrict__ Bh, const __half2* __restrict__ Bl,
    int col0B, int bKt,
    int nchunks, float acc[4][4][4])
{
    extern __shared__ char smem[];
    const int tid  = threadIdx.x;
    const int lane = tid & 31;
    const int wm   = (tid >> 5) & 1;
    const int wn   = tid >> 6;
    const uint32_t sb_u32 = smem_to_u32(smem);

    const int aRB0 = (row0A >> 4) * aKt;   // k16-region units
    const int bRB0 = (col0B >> 3) * bKt;

    auto copy_chunk = [&](int chunk) {
        const uint32_t sbase = sb_u32 + (uint32_t)(chunk % 3) * 32768u;
        for (int c = tid; c < 512; c += 256) {          // A: 16 regions x 512B
            int rr = c >> 5;
            size_t off = (size_t)(aRB0 + (rr >> 1) * aKt + chunk * 2 + (rr & 1)) * 128
                       + (size_t)((c & 31) << 2);
            uint32_t d = sbase + (uint32_t)(c << 4);
            cpasync16(d,         Ah + off);
            cpasync16(d + 8192u, Al + off);
        }
        for (int c = tid; c < 512; c += 256) {          // B: 32 regions x 256B
            int rr = c >> 4;
            size_t off = (size_t)(bRB0 + (rr >> 1) * bKt + chunk * 2 + (rr & 1)) * 64
                       + (size_t)((c & 15) << 2);
            uint32_t d = sbase + 16384u + (uint32_t)(c << 4);
            cpasync16(d,         Bh + off);
            cpasync16(d + 8192u, Bl + off);
        }
        asm volatile("cp.async.commit_group;");
    };

    // prologue: stage chunks 0,1
    copy_chunk(0);
    if (nchunks > 1) copy_chunk(1);

    for (int t = 0; t < nchunks; t++) {
        if (t + 1 < nchunks) asm volatile("cp.async.wait_group 1;");
        else                 asm volatile("cp.async.wait_group 0;");
        __syncthreads();

        // prefetch chunk t+2 (overwrites buffer of chunk t-1; its readers
        // all passed the barrier above)
        if (t + 2 < nchunks) copy_chunk(t + 2);

        const char* sb = smem + (size_t)(t % 3) * 32768;
        const uint4* pAh = (const uint4*)sb;
        const uint4* pAl = (const uint4*)(sb + 8192);
        const uint2* pBh = (const uint2*)(sb + 16384);
        const uint2* pBl = (const uint2*)(sb + 24576);

#pragma unroll
        for (int ki = 0; ki < 2; ki++) {
            uint4 fAh[4]; uint2 fBh[4];
#pragma unroll
            for (int f = 0; f < 4; f++)
                fAh[f] = pAh[((wm * 4 + f) * 2 + ki) * 32 + lane];
#pragma unroll
            for (int g = 0; g < 4; g++)
                fBh[g] = pBh[((wn * 4 + g) * 2 + ki) * 32 + lane];
            // hh
#pragma unroll
            for (int f = 0; f < 4; f++)
#pragma unroll
                for (int g = 0; g < 4; g++) mma16(acc[f][g], fAh[f], fBh[g]);
            // lh
            {
                uint4 fAl[4];
#pragma unroll
                for (int f = 0; f < 4; f++)
                    fAl[f] = pAl[((wm * 4 + f) * 2 + ki) * 32 + lane];
#pragma unroll
                for (int f = 0; f < 4; f++)
#pragma unroll
                    for (int g = 0; g < 4; g++) mma16(acc[f][g], fAl[f], fBh[g]);
            }
            // hl (skipped when NPASS == 2)
            if (NPASS == 3) {
                uint2 fBl[4];
#pragma unroll
                for (int g = 0; g < 4; g++)
                    fBl[g] = pBl[((wn * 4 + g) * 2 + ki) * 32 + lane];
#pragma unroll
                for (int f = 0; f < 4; f++)
#pragma unroll
                    for (int g = 0; g < 4; g++) mma16(acc[f][g], fAh[f], fBl[g]);
            }
        }
    }
    __syncthreads();
}
// acc coords: m = wm*64 + f*16 + (lane>>2) + 8*(r>>1); n = wn*32 + g*8 + (lane&3)*2 + (r&1)

// ===========================================================================
__global__ void __launch_bounds__(256) k_splitX(const float* __restrict__ X)
{
    int i = blockIdx.x * 256 + threadIdx.x;
    int m  = i >> 8;
    int d0 = (i & 255) << 2;
    float4 v = *(const float4*)(X + (size_t)m * DD + d0);
    wsplitA_pair(g_Xh, g_Xl, m, d0,     DD, v.x, v.y);
    wsplitA_pair(g_Xh, g_Xl, m, d0 + 2, DD, v.z, v.w);
}

__global__ void __launch_bounds__(256) k_splitW(
    const float* __restrict__ Wq, const float* __restrict__ Wk,
    const float* __restrict__ Wv)
{
    int z = blockIdx.z;
    const float* W = (z == 0) ? Wq : (z == 1) ? Wk : Wv;
    __half2* H = g_Wh + (size_t)z * DD * DD / 2;
    __half2* L = g_Wl + (size_t)z * DD * DD / 2;
    int i = blockIdx.x * 256 + threadIdx.x;
    int r2 = (i >> 10) << 1;
    int c  = i & 1023;
    float x0 = W[(size_t)r2 * DD + c];
    float x1 = W[(size_t)(r2 + 1) * DD + c];
    wsplitB_pair(H, L, r2, c, DD, x0, x1);
}

// ===========================================================================
// QKV projection. grid (DD/128, B*T/128, 3).
// ===========================================================================
__global__ void __launch_bounds__(256, 2) k_proj()
{
    const int z    = blockIdx.z;
    const int row0 = blockIdx.y * 128;
    const int col0 = blockIdx.x * 128;

    float acc[4][4][4];
#pragma unroll
    for (int f = 0; f < 4; f++)
#pragma unroll
        for (int g = 0; g < 4; g++)
#pragma unroll
            for (int r = 0; r < 4; r++) acc[f][g][r] = 0.0f;

    mma_core<3>(g_Xh, g_Xl, row0, DD >> 4,
                g_Wh + (size_t)z * DD * DD / 2, g_Wl + (size_t)z * DD * DD / 2,
                col0, DD >> 4, DD >> 5, acc);

    const int lane = threadIdx.x & 31;
    const int wm   = (threadIdx.x >> 5) & 1;
    const int wn   = threadIdx.x >> 6;
    const int mb   = row0 + wm * 64 + (lane >> 2);
    const int nb   = col0 + wn * 32 + (lane & 3) * 2;

#pragma unroll
    for (int f = 0; f < 4; f++) {
#pragma unroll
        for (int g = 0; g < 4; g++) {
            int M0 = mb + f * 16;
            int N  = nb + g * 8;
            float a0 = acc[f][g][0], a1 = acc[f][g][1];
            float a2 = acc[f][g][2], a3 = acc[f][g][3];
            if (z == 0) {
                wsplitA_pair(g_Qh, g_Ql, M0,     N, DD, a0, a1);
                wsplitA_pair(g_Qh, g_Ql, M0 + 8, N, DD, a2, a3);
            } else if (z == 1) {
                wsplitB_pair(g_Kh, g_Kl, N, M0,     DD, a0, a1);
                wsplitB_pair(g_Kh, g_Kl, N, M0 + 8, DD, a2, a3);
            } else {
#pragma unroll
                for (int r = 0; r < 4; r++) {
                    int M  = M0 + ((r >> 1) << 3);
                    int b  = M >> 11;
                    int sl = M & (TT - 1);
                    wsplitB_half(g_Vh + (size_t)b * TT * DD / 2,
                                 g_Vl + (size_t)b * TT * DD / 2,
                                 sl, N + (r & 1), TT, acc[f][g][r]);
                }
            }
        }
    }
}

// ===========================================================================
// Scores S = (Q K^T)/32, lower-triangular tiles. grid (16,16,4)
// ===========================================================================
__global__ void __launch_bounds__(256, 2) k_scores()
{
    if (blockIdx.x > blockIdx.y) return;
    const int b    = blockIdx.z;
    const int row0 = b * TT + blockIdx.y * 128;
    const int col0 = b * TT + blockIdx.x * 128;

    float acc[4][4][4];
#pragma unroll
    for (int f = 0; f < 4; f++)
#pragma unroll
        for (int g = 0; g < 4; g++)
#pragma unroll
            for (int r = 0; r < 4; r++) acc[f][g][r] = 0.0f;

    mma_core<3>(g_Qh, g_Ql, row0, DD >> 4,
                g_Kh, g_Kl, col0, DD >> 4, DD >> 5, acc);

    float* C = g_S + (size_t)b * TT * TT;
    const int lane = threadIdx.x & 31;
    const int wm   = (threadIdx.x >> 5) & 1;
    const int wn   = threadIdx.x >> 6;
    const int mb   = blockIdx.y * 128 + wm * 64 + (lane >> 2);
    const int nb   = blockIdx.x * 128 + wn * 32 + (lane & 3) * 2;

#pragma unroll
    for (int f = 0; f < 4; f++)
#pragma unroll
        for (int g = 0; g < 4; g++)
#pragma unroll
            for (int r = 0; r < 4; r++) {
                int M = mb + f * 16 + ((r >> 1) << 3);
                int N = nb + g * 8 + (r & 1);
                C[(size_t)M * TT + N] = acc[f][g][r] * 0.03125f;
            }
}

// ===========================================================================
// Causal softmax; writes split weights (A-layout) for PV.
// ===========================================================================
__global__ void __launch_bounds__(256) k_softmax()
{
    const int row = blockIdx.x;
    const int i   = row & (TT - 1);
    const float* s = g_S + (size_t)row * TT;
    const int L = i + 1;
    const int tid = threadIdx.x;
    __shared__ float red[256];

    float m = -CUDART_INF_F;
    for (int j = tid; j < L; j += 256) m = fmaxf(m, s[j]);
    red[tid] = m;
    __syncthreads();
    for (int w = 128; w > 0; w >>= 1) {
        if (tid < w) red[tid] = fmaxf(red[tid], red[tid + w]);
        __syncthreads();
    }
    m = red[0];
    __syncthreads();

    float sum = 0.0f;
    for (int j = tid; j < L; j += 256) sum += __expf(s[j] - m);
    red[tid] = sum;
    __syncthreads();
    for (int w = 128; w > 0; w >>= 1) {
        if (tid < w) red[tid] += red[tid + w];
        __syncthreads();
    }
    const float inv = 1.0f / red[0];

    for (int j4 = tid * 4; j4 < TT; j4 += 1024) {
        float w[4];
#pragma unroll
        for (int e = 0; e < 4; e++) {
            int j = j4 + e;
            w[e] = (j < L) ? __expf(s[j] - m) * inv : 0.0f;
        }
        wsplitA_pair(g_Sh, g_Sl, row, j4,     TT, w[0], w[1]);
        wsplitA_pair(g_Sh, g_Sl, row, j4 + 2, TT, w[2], w[3]);
    }
}

// ===========================================================================
// O = S_w * V, 2-pass (hh + lh), k clamped to causal extent.
// ===========================================================================
__global__ void __launch_bounds__(256, 2) k_pv(float* __restrict__ out)
{
    const int b    = blockIdx.z;
    const int row0 = b * TT + blockIdx.y * 128;
    const int col0 = blockIdx.x * 128;

    float acc[4][4][4];
#pragma unroll
    for (int f = 0; f < 4; f++)
#pragma unroll
        for (int g = 0; g < 4; g++)
#pragma unroll
            for (int r = 0; r < 4; r++) acc[f][g][r] = 0.0f;

    mma_core<2>(g_Sh, g_Sl, row0, TT >> 4,
                g_Vh + (size_t)b * TT * DD / 2, g_Vl + (size_t)b * TT * DD / 2,
                col0, TT >> 4, ((int)blockIdx.y + 1) * 4, acc);

    float* C = out + (size_t)b * TT * DD;
    const int lane = threadIdx.x & 31;
    const int wm   = (threadIdx.x >> 5) & 1;
    const int wn   = threadIdx.x >> 6;
    const int mb   = blockIdx.y * 128 + wm * 64 + (lane >> 2);
    const int nb   = col0 + wn * 32 + (lane & 3) * 2;

#pragma unroll
    for (int f = 0; f < 4; f++)
#pragma unroll
        for (int g = 0; g < 4; g++)
#pragma unroll
            for (int r = 0; r < 4; r++) {
                int M = mb + f * 16 + ((r >> 1) << 3);
                int N = nb + g * 8 + (r & 1);
                C[(size_t)M * DD + N] = acc[f][g][r];
            }
}

// ===========================================================================
extern "C" void kernel_launch(void* const* d_in, const int* in_sizes, int n_in,
                              void* d_out, int out_size)
{
    const float* X  = (const float*)d_in[0];
    const float* Wq = (const float*)d_in[1];
    const float* Wk = (const float*)d_in[2];
    const float* Wv = (const float*)d_in[3];
    float* out = (float*)d_out;

    const int SMEMB = 98304;   // 3 x 32KB buffers
    cudaFuncSetAttribute(k_proj,   cudaFuncAttributeMaxDynamicSharedMemorySize, SMEMB);
    cudaFuncSetAttribute(k_scores, cudaFuncAttributeMaxDynamicSharedMemorySize, SMEMB);
    cudaFuncSetAttribute(k_pv,     cudaFuncAttributeMaxDynamicSharedMemorySize, SMEMB);

    k_splitX <<<(BB * TT * DD) / 1024, 256>>>(X);
    k_splitW <<<dim3((DD * DD) / 512, 1, 3), 256>>>(Wq, Wk, Wv);
    k_proj   <<<dim3(DD / 128, (BB * TT) / 128, 3), 256, SMEMB>>>();
    k_scores <<<dim3(TT / 128, TT / 128, BB), 256, SMEMB>>>();
    k_softmax<<<BB * TT, 256>>>();
    k_pv     <<<dim3(DD / 128, TT / 128, BB), 256, SMEMB>>>(out);
}

// round 8
// speedup vs baseline: 3.4515x; 1.0572x over previous
#include <cuda_runtime.h>
#include <cuda_fp16.h>
#include <math_constants.h>
#include <cstdint>

#define BB 4
#define TT 2048
#define DD 1024

// ============ scratch: fp16 hi/lo split arrays in mma fragment order =======
__device__ __half2 g_Xh [(size_t)BB * TT * DD / 2];   // X, A-layout
__device__ __half2 g_Xl [(size_t)BB * TT * DD / 2];
__device__ __half2 g_XBh[(size_t)BB * TT * DD / 2];   // X, B-layout (scores B-op)
__device__ __half2 g_XBl[(size_t)BB * TT * DD / 2];
__device__ __half2 g_WqA[(size_t)DD * DD / 2];        // Wq, A-layout (hi)
__device__ __half2 g_WqAl[(size_t)DD * DD / 2];
__device__ __half2 g_WkB[(size_t)DD * DD / 2];        // Wk, B-layout (hi)
__device__ __half2 g_WkBl[(size_t)DD * DD / 2];
__device__ __half2 g_WvB[(size_t)DD * DD / 2];        // Wv, B-layout (hi)
__device__ __half2 g_WvBl[(size_t)DD * DD / 2];
__device__ __half2 g_Mh [(size_t)DD * DD / 2];        // M = Wq Wk^T, B-layout
__device__ __half2 g_Ml [(size_t)DD * DD / 2];
__device__ __half2 g_XMh[(size_t)BB * TT * DD / 2];   // XM, A-layout
__device__ __half2 g_XMl[(size_t)BB * TT * DD / 2];
__device__ __half2 g_Vh [(size_t)BB * TT * DD / 2];   // V, B-layout per batch
__device__ __half2 g_Vl [(size_t)BB * TT * DD / 2];
__device__ float   g_S  [(size_t)BB * TT * TT];
__device__ __half2 g_Sh [(size_t)BB * TT * TT / 2];
__device__ __half2 g_Sl [(size_t)BB * TT * TT / 2];

// ============================ helpers ======================================
__device__ __forceinline__ uint32_t smem_to_u32(const void* p) {
    uint32_t a;
    asm("{ .reg .u64 t; cvta.to.shared.u64 t, %1; cvt.u32.u64 %0, t; }"
        : "=r"(a) : "l"(p));
    return a;
}

__device__ __forceinline__ void mma16(float* d, uint4 a, uint2 b) {
    asm volatile(
        "mma.sync.aligned.m16n8k16.row.col.f32.f16.f16.f32 "
        "{%0,%1,%2,%3}, {%4,%5,%6,%7}, {%8,%9}, {%0,%1,%2,%3};"
        : "+f"(d[0]), "+f"(d[1]), "+f"(d[2]), "+f"(d[3])
        : "r"(a.x), "r"(a.y), "r"(a.z), "r"(a.w), "r"(b.x), "r"(b.y));
}

__device__ __forceinline__ size_t idxA32(int m, int k, int Kt) {
    return ((size_t)((m >> 4) * (Kt >> 4) + (k >> 4))) * 128
         + (size_t)((((m & 7) * 4 + ((k & 7) >> 1)) * 4)
                    + ((m >> 3) & 1) + (((k >> 3) & 1) << 1));
}
__device__ __forceinline__ size_t idxB32(int k, int n, int Kt) {
    return ((size_t)((n >> 3) * (Kt >> 4) + (k >> 4))) * 64
         + (size_t)((((n & 7) * 4 + ((k & 7) >> 1)) * 2) + ((k >> 3) & 1));
}

__device__ __forceinline__ void split1(float x, __half& h, __half& l) {
    h = __float2half_rn(x);
    l = __float2half_rn(x - __half2float(h));
}
__device__ __forceinline__ void wsplitA_pair(
    __half2* H, __half2* L, int m, int k, int Kt, float x0, float x1)
{
    __half h0, l0, h1, l1;
    split1(x0, h0, l0); split1(x1, h1, l1);
    size_t i = idxA32(m, k, Kt);
    H[i] = __halves2half2(h0, h1);
    L[i] = __halves2half2(l0, l1);
}
__device__ __forceinline__ void wsplitB_pair(
    __half2* H, __half2* L, int k, int n, int Kt, float x0, float x1)
{
    __half h0, l0, h1, l1;
    split1(x0, h0, l0); split1(x1, h1, l1);
    size_t i = idxB32(k, n, Kt);
    H[i] = __halves2half2(h0, h1);
    L[i] = __halves2half2(l0, l1);
}
__device__ __forceinline__ void wsplitB_half(
    __half2* H, __half2* L, int k, int n, int Kt, float x)
{
    __half h, l;
    split1(x, h, l);
    size_t i = idxB32(k, n, Kt) * 2 + (size_t)(k & 1);
    ((__half*)H)[i] = h;
    ((__half*)L)[i] = l;
}

__device__ __forceinline__ void cpasync16(uint32_t dst, const void* src) {
    asm volatile("cp.async.cg.shared.global [%0], [%1], 16;" :: "r"(dst), "l"(src));
}

// ===========================================================================
// MMA core (unchanged engine): acc += A[128 x 32*nchunks] * B^T, split passes.
// NPASS=3: hh+lh+hl; NPASS=2: hh+lh. 3-stage cp.async, 1 barrier/chunk.
// ===========================================================================
template<int NPASS>
__device__ __forceinline__ void mma_core(
    const __half2* __restrict__ Ah, const __half2* __restrict__ Al,
    int row0A, int aKt,
    const __half2* __restrict__ Bh, const __half2* __restrict__ Bl,
    int col0B, int bKt,
    int nchunks, float acc[4][4][4])
{
    extern __shared__ char smem[];
    const int tid  = threadIdx.x;
    const int lane = tid & 31;
    const int wm   = (tid >> 5) & 1;
    const int wn   = tid >> 6;
    const uint32_t sb_u32 = smem_to_u32(smem);

    const int aRB0 = (row0A >> 4) * aKt;
    const int bRB0 = (col0B >> 3) * bKt;

    auto copy_chunk = [&](int chunk) {
        const uint32_t sbase = sb_u32 + (uint32_t)(chunk % 3) * 32768u;
        for (int c = tid; c < 512; c += 256) {
            int rr = c >> 5;
            size_t off = (size_t)(aRB0 + (rr >> 1) * aKt + chunk * 2 + (rr & 1)) * 128
                       + (size_t)((c & 31) << 2);
            uint32_t d = sbase + (uint32_t)(c << 4);
            cpasync16(d,         Ah + off);
            cpasync16(d + 8192u, Al + off);
        }
        for (int c = tid; c < 512; c += 256) {
            int rr = c >> 4;
            size_t off = (size_t)(bRB0 + (rr >> 1) * bKt + chunk * 2 + (rr & 1)) * 64
                       + (size_t)((c & 15) << 2);
            uint32_t d = sbase + 16384u + (uint32_t)(c << 4);
            cpasync16(d,         Bh + off);
            cpasync16(d + 8192u, Bl + off);
        }
        asm volatile("cp.async.commit_group;");
    };

    copy_chunk(0);
    if (nchunks > 1) copy_chunk(1);

    for (int t = 0; t < nchunks; t++) {
        if (t + 1 < nchunks) asm volatile("cp.async.wait_group 1;");
        else                 asm volatile("cp.async.wait_group 0;");
        __syncthreads();

        if (t + 2 < nchunks) copy_chunk(t + 2);

        const char* sb = smem + (size_t)(t % 3) * 32768;
        const uint4* pAh = (const uint4*)sb;
        const uint4* pAl = (const uint4*)(sb + 8192);
        const uint2* pBh = (const uint2*)(sb + 16384);
        const uint2* pBl = (const uint2*)(sb + 24576);

#pragma unroll
        for (int ki = 0; ki < 2; ki++) {
            uint4 fAh[4]; uint2 fBh[4];
#pragma unroll
            for (int f = 0; f < 4; f++)
                fAh[f] = pAh[((wm * 4 + f) * 2 + ki) * 32 + lane];
#pragma unroll
            for (int g = 0; g < 4; g++)
                fBh[g] = pBh[((wn * 4 + g) * 2 + ki) * 32 + lane];
#pragma unroll
            for (int f = 0; f < 4; f++)
#pragma unroll
                for (int g = 0; g < 4; g++) mma16(acc[f][g], fAh[f], fBh[g]);
            {
                uint4 fAl[4];
#pragma unroll
                for (int f = 0; f < 4; f++)
                    fAl[f] = pAl[((wm * 4 + f) * 2 + ki) * 32 + lane];
#pragma unroll
                for (int f = 0; f < 4; f++)
#pragma unroll
                    for (int g = 0; g < 4; g++) mma16(acc[f][g], fAl[f], fBh[g]);
            }
            if (NPASS == 3) {
                uint2 fBl[4];
#pragma unroll
                for (int g = 0; g < 4; g++)
                    fBl[g] = pBl[((wn * 4 + g) * 2 + ki) * 32 + lane];
#pragma unroll
                for (int f = 0; f < 4; f++)
#pragma unroll
                    for (int g = 0; g < 4; g++) mma16(acc[f][g], fAh[f], fBl[g]);
            }
        }
    }
    __syncthreads();
}
// acc coords: m = wm*64 + f*16 + (lane>>2) + 8*(r>>1); n = wn*32 + g*8 + (lane&3)*2 + (r&1)

#define ACC_DECL float acc[4][4][4]; \
    _Pragma("unroll") for (int f = 0; f < 4; f++) \
    _Pragma("unroll") for (int g = 0; g < 4; g++) \
    _Pragma("unroll") for (int r = 0; r < 4; r++) acc[f][g][r] = 0.0f;

// ===========================================================================
// Splits
// ===========================================================================
__global__ void __launch_bounds__(256) k_splitX(const float* __restrict__ X)
{
    int i = blockIdx.x * 256 + threadIdx.x;      // over (BB*TT*DD)/4 float4s
    int m  = i >> 8;
    int d0 = (i & 255) << 2;
    float4 v = *(const float4*)(X + (size_t)m * DD + d0);
    wsplitA_pair(g_Xh,  g_Xl,  m, d0,     DD, v.x, v.y);
    wsplitA_pair(g_Xh,  g_Xl,  m, d0 + 2, DD, v.z, v.w);
    wsplitB_pair(g_XBh, g_XBl, d0,     m, DD, v.x, v.y);
    wsplitB_pair(g_XBh, g_XBl, d0 + 2, m, DD, v.z, v.w);
}

__global__ void __launch_bounds__(256) k_splitWq(const float* __restrict__ Wq)
{
    int i = blockIdx.x * 256 + threadIdx.x;      // over DD*DD/4
    int d  = i >> 8;
    int j0 = (i & 255) << 2;
    float4 v = *(const float4*)(Wq + (size_t)d * DD + j0);
    wsplitA_pair(g_WqA, g_WqAl, d, j0,     DD, v.x, v.y);
    wsplitA_pair(g_WqA, g_WqAl, d, j0 + 2, DD, v.z, v.w);
}

__global__ void __launch_bounds__(256) k_splitWk(const float* __restrict__ Wk)
{
    int i = blockIdx.x * 256 + threadIdx.x;      // over DD*DD/4
    int e  = i >> 8;
    int j0 = (i & 255) << 2;
    float4 v = *(const float4*)(Wk + (size_t)e * DD + j0);
    wsplitB_pair(g_WkB, g_WkBl, j0,     e, DD, v.x, v.y);
    wsplitB_pair(g_WkB, g_WkBl, j0 + 2, e, DD, v.z, v.w);
}

__global__ void __launch_bounds__(256) k_splitWv(const float* __restrict__ Wv)
{
    int i = blockIdx.x * 256 + threadIdx.x;      // over DD*DD/2 (k-pairs)
    int r2 = (i >> 10) << 1;
    int c  = i & 1023;
    float x0 = Wv[(size_t)r2 * DD + c];
    float x1 = Wv[(size_t)(r2 + 1) * DD + c];
    wsplitB_pair(g_WvB, g_WvBl, r2, c, DD, x0, x1);
}

// ===========================================================================
// M = Wq @ Wk^T (1024x1024), 3-pass. grid (8, 8). Epilogue -> B-layout split.
// ===========================================================================
__global__ void __launch_bounds__(256, 2) k_gemmM()
{
    const int row0 = blockIdx.y * 128;   // d
    const int col0 = blockIdx.x * 128;   // e
    ACC_DECL;
    mma_core<3>(g_WqA, g_WqAl, row0, DD >> 4,
                g_WkB, g_WkBl, col0, DD >> 4, DD >> 5, acc);

    const int lane = threadIdx.x & 31;
    const int wm   = (threadIdx.x >> 5) & 1;
    const int wn   = threadIdx.x >> 6;
    const int mb   = row0 + wm * 64 + (lane >> 2);
    const int nb   = col0 + wn * 32 + (lane & 3) * 2;
#pragma unroll
    for (int f = 0; f < 4; f++)
#pragma unroll
        for (int g = 0; g < 4; g++)
#pragma unroll
            for (int r = 0; r < 4; r++) {
                int Md = mb + f * 16 + ((r >> 1) << 3);
                int Ne = nb + g * 8 + (r & 1);
                wsplitB_half(g_Mh, g_Ml, Md, Ne, DD, acc[f][g][r]);
            }
}

// ===========================================================================
// XM = X @ M. grid (8, 64). Epilogue -> A-layout split.
// ===========================================================================
__global__ void __launch_bounds__(256, 2) k_xm()
{
    const int row0 = blockIdx.y * 128;
    const int col0 = blockIdx.x * 128;
    ACC_DECL;
    mma_core<3>(g_Xh, g_Xl, row0, DD >> 4,
                g_Mh, g_Ml, col0, DD >> 4, DD >> 5, acc);

    const int lane = threadIdx.x & 31;
    const int wm   = (threadIdx.x >> 5) & 1;
    const int wn   = threadIdx.x >> 6;
    const int mb   = row0 + wm * 64 + (lane >> 2);
    const int nb   = col0 + wn * 32 + (lane & 3) * 2;
#pragma unroll
    for (int f = 0; f < 4; f++)
#pragma unroll
        for (int g = 0; g < 4; g++) {
            int M0 = mb + f * 16;
            int N  = nb + g * 8;
            wsplitA_pair(g_XMh, g_XMl, M0,     N, DD, acc[f][g][0], acc[f][g][1]);
            wsplitA_pair(g_XMh, g_XMl, M0 + 8, N, DD, acc[f][g][2], acc[f][g][3]);
        }
}

// ===========================================================================
// V = X @ Wv. grid (8, 64). Epilogue -> per-batch B-layout split (k = token).
// ===========================================================================
__global__ void __launch_bounds__(256, 2) k_projV()
{
    const int row0 = blockIdx.y * 128;
    const int col0 = blockIdx.x * 128;
    ACC_DECL;
    mma_core<3>(g_Xh, g_Xl, row0, DD >> 4,
                g_WvB, g_WvBl, col0, DD >> 4, DD >> 5, acc);

    const int lane = threadIdx.x & 31;
    const int wm   = (threadIdx.x >> 5) & 1;
    const int wn   = threadIdx.x >> 6;
    const int mb   = row0 + wm * 64 + (lane >> 2);
    const int nb   = col0 + wn * 32 + (lane & 3) * 2;
#pragma unroll
    for (int f = 0; f < 4; f++)
#pragma unroll
        for (int g = 0; g < 4; g++)
#pragma unroll
            for (int r = 0; r < 4; r++) {
                int Mg = mb + f * 16 + ((r >> 1) << 3);
                int b  = Mg >> 11;
                int sl = Mg & (TT - 1);
                wsplitB_half(g_Vh + (size_t)b * TT * DD / 2,
                             g_Vl + (size_t)b * TT * DD / 2,
                             sl, nb + g * 8 + (r & 1), TT, acc[f][g][r]);
            }
}

// ===========================================================================
// Scores S = (XM @ X^T)/32, lower-triangular tiles. grid (16,16,4)
// ===========================================================================
__global__ void __launch_bounds__(256, 2) k_scores()
{
    if (blockIdx.x > blockIdx.y) return;
    const int b    = blockIdx.z;
    const int row0 = b * TT + blockIdx.y * 128;
    const int col0 = b * TT + blockIdx.x * 128;
    ACC_DECL;
    mma_core<3>(g_XMh, g_XMl, row0, DD >> 4,
                g_XBh, g_XBl, col0, DD >> 4, DD >> 5, acc);

    float* C = g_S + (size_t)b * TT * TT;
    const int lane = threadIdx.x & 31;
    const int wm   = (threadIdx.x >> 5) & 1;
    const int wn   = threadIdx.x >> 6;
    const int mb   = blockIdx.y * 128 + wm * 64 + (lane >> 2);
    const int nb   = blockIdx.x * 128 + wn * 32 + (lane & 3) * 2;
#pragma unroll
    for (int f = 0; f < 4; f++)
#pragma unroll
        for (int g = 0; g < 4; g++)
#pragma unroll
            for (int r = 0; r < 4; r++) {
                int M = mb + f * 16 + ((r >> 1) << 3);
                int N = nb + g * 8 + (r & 1);
                C[(size_t)M * TT + N] = acc[f][g][r] * 0.03125f;
            }
}

// ===========================================================================
// Causal softmax; writes split weights (A-layout) for PV.
// ===========================================================================
__global__ void __launch_bounds__(256) k_softmax()
{
    const int row = blockIdx.x;
    const int i   = row & (TT - 1);
    const float* s = g_S + (size_t)row * TT;
    const int L = i + 1;
    const int tid = threadIdx.x;
    __shared__ float red[256];

    float m = -CUDART_INF_F;
    for (int j = tid; j < L; j += 256) m = fmaxf(m, s[j]);
    red[tid] = m;
    __syncthreads();
    for (int w = 128; w > 0; w >>= 1) {
        if (tid < w) red[tid] = fmaxf(red[tid], red[tid + w]);
        __syncthreads();
    }
    m = red[0];
    __syncthreads();

    float sum = 0.0f;
    for (int j = tid; j < L; j += 256) sum += __expf(s[j] - m);
    red[tid] = sum;
    __syncthreads();
    for (int w = 128; w > 0; w >>= 1) {
        if (tid < w) red[tid] += red[tid + w];
        __syncthreads();
    }
    const float inv = 1.0f / red[0];

    for (int j4 = tid * 4; j4 < TT; j4 += 1024) {
        float w[4];
#pragma unroll
        for (int e = 0; e < 4; e++) {
            int j = j4 + e;
            w[e] = (j < L) ? __expf(s[j] - m) * inv : 0.0f;
        }
        wsplitA_pair(g_Sh, g_Sl, row, j4,     TT, w[0], w[1]);
        wsplitA_pair(g_Sh, g_Sl, row, j4 + 2, TT, w[2], w[3]);
    }
}

// ===========================================================================
// O = S_w * V, 2-pass, k clamped to causal extent. grid (8, 16, 4)
// ===========================================================================
__global__ void __launch_bounds__(256, 2) k_pv(float* __restrict__ out)
{
    const int b    = blockIdx.z;
    const int row0 = b * TT + blockIdx.y * 128;
    const int col0 = blockIdx.x * 128;
    ACC_DECL;
    mma_core<2>(g_Sh, g_Sl, row0, TT >> 4,
                g_Vh + (size_t)b * TT * DD / 2, g_Vl + (size_t)b * TT * DD / 2,
                col0, TT >> 4, ((int)blockIdx.y + 1) * 4, acc);

    float* C = out + (size_t)b * TT * DD;
    const int lane = threadIdx.x & 31;
    const int wm   = (threadIdx.x >> 5) & 1;
    const int wn   = threadIdx.x >> 6;
    const int mb   = blockIdx.y * 128 + wm * 64 + (lane >> 2);
    const int nb   = col0 + wn * 32 + (lane & 3) * 2;
#pragma unroll
    for (int f = 0; f < 4; f++)
#pragma unroll
        for (int g = 0; g < 4; g++)
#pragma unroll
            for (int r = 0; r < 4; r++) {
                int M = mb + f * 16 + ((r >> 1) << 3);
                int N = nb + g * 8 + (r & 1);
                C[(size_t)M * DD + N] = acc[f][g][r];
            }
}

// ===========================================================================
extern "C" void kernel_launch(void* const* d_in, const int* in_sizes, int n_in,
                              void* d_out, int out_size)
{
    const float* X  = (const float*)d_in[0];
    const float* Wq = (const float*)d_in[1];
    const float* Wk = (const float*)d_in[2];
    const float* Wv = (const float*)d_in[3];
    float* out = (float*)d_out;

    const int SMEMB = 98304;   // 3 x 32KB buffers
    cudaFuncSetAttribute(k_gemmM, cudaFuncAttributeMaxDynamicSharedMemorySize, SMEMB);
    cudaFuncSetAttribute(k_xm,    cudaFuncAttributeMaxDynamicSharedMemorySize, SMEMB);
    cudaFuncSetAttribute(k_projV, cudaFuncAttributeMaxDynamicSharedMemorySize, SMEMB);
    cudaFuncSetAttribute(k_scores,cudaFuncAttributeMaxDynamicSharedMemorySize, SMEMB);
    cudaFuncSetAttribute(k_pv,    cudaFuncAttributeMaxDynamicSharedMemorySize, SMEMB);

    k_splitX <<<(BB * TT * DD) / 1024, 256>>>(X);
    k_splitWq<<<(DD * DD) / 1024, 256>>>(Wq);
    k_splitWk<<<(DD * DD) / 1024, 256>>>(Wk);
    k_splitWv<<<(DD * DD) / 512, 256>>>(Wv);
    k_gemmM  <<<dim3(DD / 128, DD / 128), 256, SMEMB>>>();
    k_projV  <<<dim3(DD / 128, (BB * TT) / 128), 256, SMEMB>>>();
    k_xm     <<<dim3(DD / 128, (BB * TT) / 128), 256, SMEMB>>>();
    k_scores <<<dim3(TT / 128, TT / 128, BB), 256, SMEMB>>>();
    k_softmax<<<BB * TT, 256>>>();
    k_pv     <<<dim3(DD / 128, TT / 128, BB), 256, SMEMB>>>(out);
}

// round 10
// speedup vs baseline: 3.4889x; 1.0108x over previous
#include <cuda_runtime.h>
#include <cuda_fp16.h>
#include <math_constants.h>
#include <cstdint>

#define BB 4
#define TT 2048
#define DD 1024

// ============ scratch: fp16 hi/lo split arrays in mma fragment order =======
__device__ __half2 g_Xh [(size_t)BB * TT * DD / 2];   // X, A-layout
__device__ __half2 g_Xl [(size_t)BB * TT * DD / 2];
__device__ __half2 g_XBh[(size_t)BB * TT * DD / 2];   // X, B-layout
__device__ __half2 g_XBl[(size_t)BB * TT * DD / 2];
__device__ __half2 g_WqA[(size_t)DD * DD / 2];
__device__ __half2 g_WqAl[(size_t)DD * DD / 2];
__device__ __half2 g_WkB[(size_t)DD * DD / 2];
__device__ __half2 g_WkBl[(size_t)DD * DD / 2];
__device__ __half2 g_WvB[(size_t)DD * DD / 2];
__device__ __half2 g_WvBl[(size_t)DD * DD / 2];
__device__ __half2 g_Mh [(size_t)DD * DD / 2];        // M = Wq Wk^T, B-layout
__device__ __half2 g_Ml [(size_t)DD * DD / 2];
__device__ __half2 g_XMh[(size_t)BB * TT * DD / 2];   // XM, A-layout
__device__ __half2 g_XMl[(size_t)BB * TT * DD / 2];
__device__ __half2 g_Vh [(size_t)BB * TT * DD / 2];   // V, B-layout per batch
__device__ __half2 g_Vl [(size_t)BB * TT * DD / 2];
__device__ float   g_S  [(size_t)BB * TT * TT];
__device__ __half2 g_Sh [(size_t)BB * TT * TT / 2];
__device__ __half2 g_Sl [(size_t)BB * TT * TT / 2];
__device__ float   g_rowM[(size_t)BB * TT];
__device__ float   g_rowI[(size_t)BB * TT];

// ============================ helpers ======================================
__device__ __forceinline__ uint32_t smem_to_u32(const void* p) {
    uint32_t a;
    asm("{ .reg .u64 t; cvta.to.shared.u64 t, %1; cvt.u32.u64 %0, t; }"
        : "=r"(a) : "l"(p));
    return a;
}

__device__ __forceinline__ void mma16(float* d, uint4 a, uint2 b) {
    asm volatile(
        "mma.sync.aligned.m16n8k16.row.col.f32.f16.f16.f32 "
        "{%0,%1,%2,%3}, {%4,%5,%6,%7}, {%8,%9}, {%0,%1,%2,%3};"
        : "+f"(d[0]), "+f"(d[1]), "+f"(d[2]), "+f"(d[3])
        : "r"(a.x), "r"(a.y), "r"(a.z), "r"(a.w), "r"(b.x), "r"(b.y));
}

__device__ __forceinline__ size_t idxA32(int m, int k, int Kt) {
    return ((size_t)((m >> 4) * (Kt >> 4) + (k >> 4))) * 128
         + (size_t)((((m & 7) * 4 + ((k & 7) >> 1)) * 4)
                    + ((m >> 3) & 1) + (((k >> 3) & 1) << 1));
}
__device__ __forceinline__ size_t idxB32(int k, int n, int Kt) {
    return ((size_t)((n >> 3) * (Kt >> 4) + (k >> 4))) * 64
         + (size_t)((((n & 7) * 4 + ((k & 7) >> 1)) * 2) + ((k >> 3) & 1));
}

__device__ __forceinline__ void split1(float x, __half& h, __half& l) {
    h = __float2half_rn(x);
    l = __float2half_rn(x - __half2float(h));
}
__device__ __forceinline__ void wsplitA_pair(
    __half2* H, __half2* L, int m, int k, int Kt, float x0, float x1)
{
    __half h0, l0, h1, l1;
    split1(x0, h0, l0); split1(x1, h1, l1);
    size_t i = idxA32(m, k, Kt);
    H[i] = __halves2half2(h0, h1);
    L[i] = __halves2half2(l0, l1);
}
__device__ __forceinline__ void wsplitB_pair(
    __half2* H, __half2* L, int k, int n, int Kt, float x0, float x1)
{
    __half h0, l0, h1, l1;
    split1(x0, h0, l0); split1(x1, h1, l1);
    size_t i = idxB32(k, n, Kt);
    H[i] = __halves2half2(h0, h1);
    L[i] = __halves2half2(l0, l1);
}
__device__ __forceinline__ void wsplitB_half(
    __half2* H, __half2* L, int k, int n, int Kt, float x)
{
    __half h, l;
    split1(x, h, l);
    size_t i = idxB32(k, n, Kt) * 2 + (size_t)(k & 1);
    ((__half*)H)[i] = h;
    ((__half*)L)[i] = l;
}

__device__ __forceinline__ void cpasync16(uint32_t dst, const void* src) {
    asm volatile("cp.async.cg.shared.global [%0], [%1], 16;" :: "r"(dst), "l"(src));
}

// ===========================================================================
// MMA core (unchanged engine)
// ===========================================================================
template<int NPASS>
__device__ __forceinline__ void mma_core(
    const __half2* __restrict__ Ah, const __half2* __restrict__ Al,
    int row0A, int aKt,
    const __half2* __restrict__ Bh, const __half2* __restrict__ Bl,
    int col0B, int bKt,
    int nchunks, float acc[4][4][4])
{
    extern __shared__ char smem[];
    const int tid  = threadIdx.x;
    const int lane = tid & 31;
    const int wm   = (tid >> 5) & 1;
    const int wn   = tid >> 6;
    const uint32_t sb_u32 = smem_to_u32(smem);

    const int aRB0 = (row0A >> 4) * aKt;
    const int bRB0 = (col0B >> 3) * bKt;

    auto copy_chunk = [&](int chunk) {
        const uint32_t sbase = sb_u32 + (uint32_t)(chunk % 3) * 32768u;
        for (int c = tid; c < 512; c += 256) {
            int rr = c >> 5;
            size_t off = (size_t)(aRB0 + (rr >> 1) * aKt + chunk * 2 + (rr & 1)) * 128
                       + (size_t)((c & 31) << 2);
            uint32_t d = sbase + (uint32_t)(c << 4);
            cpasync16(d,         Ah + off);
            cpasync16(d + 8192u, Al + off);
        }
        for (int c = tid; c < 512; c += 256) {
            int rr = c >> 4;
            size_t off = (size_t)(bRB0 + (rr >> 1) * bKt + chunk * 2 + (rr & 1)) * 64
                       + (size_t)((c & 15) << 2);
            uint32_t d = sbase + 16384u + (uint32_t)(c << 4);
            cpasync16(d,         Bh + off);
            cpasync16(d + 8192u, Bl + off);
        }
        asm volatile("cp.async.commit_group;");
    };

    copy_chunk(0);
    if (nchunks > 1) copy_chunk(1);

    for (int t = 0; t < nchunks; t++) {
        if (t + 1 < nchunks) asm volatile("cp.async.wait_group 1;");
        else                 asm volatile("cp.async.wait_group 0;");
        __syncthreads();

        if (t + 2 < nchunks) copy_chunk(t + 2);

        const char* sb = smem + (size_t)(t % 3) * 32768;
        const uint4* pAh = (const uint4*)sb;
        const uint4* pAl = (const uint4*)(sb + 8192);
        const uint2* pBh = (const uint2*)(sb + 16384);
        const uint2* pBl = (const uint2*)(sb + 24576);

#pragma unroll
        for (int ki = 0; ki < 2; ki++) {
            uint4 fAh[4]; uint2 fBh[4];
#pragma unroll
            for (int f = 0; f < 4; f++)
                fAh[f] = pAh[((wm * 4 + f) * 2 + ki) * 32 + lane];
#pragma unroll
            for (int g = 0; g < 4; g++)
                fBh[g] = pBh[((wn * 4 + g) * 2 + ki) * 32 + lane];
#pragma unroll
            for (int f = 0; f < 4; f++)
#pragma unroll
                for (int g = 0; g < 4; g++) mma16(acc[f][g], fAh[f], fBh[g]);
            {
                uint4 fAl[4];
#pragma unroll
                for (int f = 0; f < 4; f++)
                    fAl[f] = pAl[((wm * 4 + f) * 2 + ki) * 32 + lane];
#pragma unroll
                for (int f = 0; f < 4; f++)
#pragma unroll
                    for (int g = 0; g < 4; g++) mma16(acc[f][g], fAl[f], fBh[g]);
            }
            if (NPASS == 3) {
                uint2 fBl[4];
#pragma unroll
                for (int g = 0; g < 4; g++)
                    fBl[g] = pBl[((wn * 4 + g) * 2 + ki) * 32 + lane];
#pragma unroll
                for (int f = 0; f < 4; f++)
#pragma unroll
                    for (int g = 0; g < 4; g++) mma16(acc[f][g], fAh[f], fBl[g]);
            }
        }
    }
    __syncthreads();
}
// acc coords: m = wm*64 + f*16 + (lane>>2) + 8*(r>>1); n = wn*32 + g*8 + (lane&3)*2 + (r&1)

#define ACC_DECL float acc[4][4][4]; \
    _Pragma("unroll") for (int f = 0; f < 4; f++) \
    _Pragma("unroll") for (int g = 0; g < 4; g++) \
    _Pragma("unroll") for (int r = 0; r < 4; r++) acc[f][g][r] = 0.0f;

// ===========================================================================
// Splits
// ===========================================================================
__global__ void __launch_bounds__(256) k_splitX(const float* __restrict__ X)
{
    int i = blockIdx.x * 256 + threadIdx.x;
    int m  = i >> 8;
    int d0 = (i & 255) << 2;
    float4 v = *(const float4*)(X + (size_t)m * DD + d0);
    wsplitA_pair(g_Xh,  g_Xl,  m, d0,     DD, v.x, v.y);
    wsplitA_pair(g_Xh,  g_Xl,  m, d0 + 2, DD, v.z, v.w);
    wsplitB_pair(g_XBh, g_XBl, d0,     m, DD, v.x, v.y);
    wsplitB_pair(g_XBh, g_XBl, d0 + 2, m, DD, v.z, v.w);
}

__global__ void __launch_bounds__(256) k_splitWq(const float* __restrict__ Wq)
{
    int i = blockIdx.x * 256 + threadIdx.x;
    int d  = i >> 8;
    int j0 = (i & 255) << 2;
    float4 v = *(const float4*)(Wq + (size_t)d * DD + j0);
    wsplitA_pair(g_WqA, g_WqAl, d, j0,     DD, v.x, v.y);
    wsplitA_pair(g_WqA, g_WqAl, d, j0 + 2, DD, v.z, v.w);
}

__global__ void __launch_bounds__(256) k_splitWk(const float* __restrict__ Wk)
{
    int i = blockIdx.x * 256 + threadIdx.x;
    int e  = i >> 8;
    int j0 = (i & 255) << 2;
    float4 v = *(const float4*)(Wk + (size_t)e * DD + j0);
    wsplitB_pair(g_WkB, g_WkBl, j0,     e, DD, v.x, v.y);
    wsplitB_pair(g_WkB, g_WkBl, j0 + 2, e, DD, v.z, v.w);
}

__global__ void __launch_bounds__(256) k_splitWv(const float* __restrict__ Wv)
{
    int i = blockIdx.x * 256 + threadIdx.x;
    int r2 = (i >> 10) << 1;
    int c  = i & 1023;
    float x0 = Wv[(size_t)r2 * DD + c];
    float x1 = Wv[(size_t)(r2 + 1) * DD + c];
    wsplitB_pair(g_WvB, g_WvBl, r2, c, DD, x0, x1);
}

// ===========================================================================
// M = Wq @ Wk^T. grid (8, 8).
// ===========================================================================
__global__ void __launch_bounds__(256, 2) k_gemmM()
{
    const int row0 = blockIdx.y * 128;
    const int col0 = blockIdx.x * 128;
    ACC_DECL;
    mma_core<3>(g_WqA, g_WqAl, row0, DD >> 4,
                g_WkB, g_WkBl, col0, DD >> 4, DD >> 5, acc);

    const int lane = threadIdx.x & 31;
    const int wm   = (threadIdx.x >> 5) & 1;
    const int wn   = threadIdx.x >> 6;
    const int mb   = row0 + wm * 64 + (lane >> 2);
    const int nb   = col0 + wn * 32 + (lane & 3) * 2;
#pragma unroll
    for (int f = 0; f < 4; f++)
#pragma unroll
        for (int g = 0; g < 4; g++)
#pragma unroll
            for (int r = 0; r < 4; r++) {
                int Md = mb + f * 16 + ((r >> 1) << 3);
                int Ne = nb + g * 8 + (r & 1);
                wsplitB_half(g_Mh, g_Ml, Md, Ne, DD, acc[f][g][r]);
            }
}

// ===========================================================================
// XM = X @ M. grid (8, 64).
// ===========================================================================
__global__ void __launch_bounds__(256, 2) k_xm()
{
    const int row0 = blockIdx.y * 128;
    const int col0 = blockIdx.x * 128;
    ACC_DECL;
    mma_core<3>(g_Xh, g_Xl, row0, DD >> 4,
                g_Mh, g_Ml, col0, DD >> 4, DD >> 5, acc);

    const int lane = threadIdx.x & 31;
    const int wm   = (threadIdx.x >> 5) & 1;
    const int wn   = threadIdx.x >> 6;
    const int mb   = row0 + wm * 64 + (lane >> 2);
    const int nb   = col0 + wn * 32 + (lane & 3) * 2;
#pragma unroll
    for (int f = 0; f < 4; f++)
#pragma unroll
        for (int g = 0; g < 4; g++) {
            int M0 = mb + f * 16;
            int N  = nb + g * 8;
            wsplitA_pair(g_XMh, g_XMl, M0,     N, DD, acc[f][g][0], acc[f][g][1]);
            wsplitA_pair(g_XMh, g_XMl, M0 + 8, N, DD, acc[f][g][2], acc[f][g][3]);
        }
}

// ===========================================================================
// V = X @ Wv. grid (8, 64).
// ===========================================================================
__global__ void __launch_bounds__(256, 2) k_projV()
{
    const int row0 = blockIdx.y * 128;
    const int col0 = blockIdx.x * 128;
    ACC_DECL;
    mma_core<3>(g_Xh, g_Xl, row0, DD >> 4,
                g_WvB, g_WvBl, col0, DD >> 4, DD >> 5, acc);

    const int lane = threadIdx.x & 31;
    const int wm   = (threadIdx.x >> 5) & 1;
    const int wn   = threadIdx.x >> 6;
    const int mb   = row0 + wm * 64 + (lane >> 2);
    const int nb   = col0 + wn * 32 + (lane & 3) * 2;
#pragma unroll
    for (int f = 0; f < 4; f++)
#pragma unroll
        for (int g = 0; g < 4; g++)
#pragma unroll
            for (int r = 0; r < 4; r++) {
                int Mg = mb + f * 16 + ((r >> 1) << 3);
                int b  = Mg >> 11;
                int sl = Mg & (TT - 1);
                wsplitB_half(g_Vh + (size_t)b * TT * DD / 2,
                             g_Vl + (size_t)b * TT * DD / 2,
                             sl, nb + g * 8 + (r & 1), TT, acc[f][g][r]);
            }
}

// ===========================================================================
// Scores S = (XM @ X^T)/32, lower-triangular tiles. grid (16,16,4)
// ===========================================================================
__global__ void __launch_bounds__(256, 2) k_scores()
{
    if (blockIdx.x > blockIdx.y) return;
    const int b    = blockIdx.z;
    const int row0 = b * TT + blockIdx.y * 128;
    const int col0 = b * TT + blockIdx.x * 128;
    ACC_DECL;
    mma_core<3>(g_XMh, g_XMl, row0, DD >> 4,
                g_XBh, g_XBl, col0, DD >> 4, DD >> 5, acc);

    float* C = g_S + (size_t)b * TT * TT;
    const int lane = threadIdx.x & 31;
    const int wm   = (threadIdx.x >> 5) & 1;
    const int wn   = threadIdx.x >> 6;
    const int mb   = blockIdx.y * 128 + wm * 64 + (lane >> 2);
    const int nb   = blockIdx.x * 128 + wn * 32 + (lane & 3) * 2;
#pragma unroll
    for (int f = 0; f < 4; f++)
#pragma unroll
        for (int g = 0; g < 4; g++)
#pragma unroll
            for (int r = 0; r < 4; r++) {
                int M = mb + f * 16 + ((r >> 1) << 3);
                int N = nb + g * 8 + (r & 1);
                C[(size_t)M * TT + N] = acc[f][g][r] * 0.03125f;
            }
}

// ===========================================================================
// Phase 1 softmax: per-row max and 1/sum. grid = B*T, 256 thr.
// ===========================================================================
__global__ void __launch_bounds__(256) k_rowstat()
{
    const int row = blockIdx.x;
    const int i   = row & (TT - 1);
    const float* s = g_S + (size_t)row * TT;
    const int L = i + 1;
    const int tid = threadIdx.x;
    __shared__ float red[256];

    float m = -CUDART_INF_F;
    for (int j = tid; j < L; j += 256) m = fmaxf(m, s[j]);
    red[tid] = m;
    __syncthreads();
    for (int w = 128; w > 0; w >>= 1) {
        if (tid < w) red[tid] = fmaxf(red[tid], red[tid + w]);
        __syncthreads();
    }
    m = red[0];
    __syncthreads();

    float sum = 0.0f;
    for (int j = tid; j < L; j += 256) sum += __expf(s[j] - m);
    red[tid] = sum;
    __syncthreads();
    for (int w = 128; w > 0; w >>= 1) {
        if (tid < w) red[tid] += red[tid + w];
        __syncthreads();
    }
    if (tid == 0) {
        g_rowM[row] = m;
        g_rowI[row] = 1.0f / red[0];
    }
}

// ===========================================================================
// Phase 2 softmax: per lower-tri tile, compute w = exp(s-m)*inv and write
// Sh/Sl in A-layout with FULLY COALESCED uint4 region stores.
// grid (16,16,4), bx <= by. Dynamic smem: S tile 128x132 f32 + rowM/rowI.
// ===========================================================================
__global__ void __launch_bounds__(256) k_wsplit()
{
    if (blockIdx.x > blockIdx.y) return;
    extern __shared__ float sws[];
    float* sS = sws;                    // 128 * 132
    float* sM = sws + 128 * 132;        // 128
    float* sI = sM + 128;               // 128

    const int b  = blockIdx.z;
    const int by = blockIdx.y;
    const int bx = blockIdx.x;
    const int tid = threadIdx.x;
    const int row0 = by * 128;
    const int col0 = bx * 128;
    const float* S = g_S + (size_t)b * TT * TT;

    for (int i = tid; i < 4096; i += 256) {
        int r  = i >> 5;
        int c4 = (i & 31) << 2;
        float4 v = *(const float4*)(S + (size_t)(row0 + r) * TT + col0 + c4);
        sS[r * 132 + c4 + 0] = v.x;
        sS[r * 132 + c4 + 1] = v.y;
        sS[r * 132 + c4 + 2] = v.z;
        sS[r * 132 + c4 + 3] = v.w;
    }
    if (tid < 128) {
        sM[tid] = g_rowM[b * TT + row0 + tid];
        sI[tid] = g_rowI[b * TT + row0 + tid];
    }
    __syncthreads();

    const int w    = tid >> 5;          // warp = m16-region index (0..7)
    const int lane = tid & 31;
    const bool diag = (bx == by);

    for (int kreg = 0; kreg < 8; kreg++) {
        // global A-layout region id: ((globalRow>>4) * (TT>>4)) + globalK>>4
        const size_t Rg = ((size_t)(b * 128 + by * 8 + w)) * 128 + (size_t)(bx * 8 + kreg);
        uint32_t hv[4], lv[4];
#pragma unroll
        for (int j = 0; j < 4; j++) {
            int m = w * 16 + (lane >> 2) + 8 * (j & 1);
            int k = kreg * 16 + (lane & 3) * 2 + 8 * ((j >> 1) & 1);
            float mx  = sM[m];
            float inv = sI[m];
            float w0 = __expf(sS[m * 132 + k]     - mx) * inv;
            float w1 = __expf(sS[m * 132 + k + 1] - mx) * inv;
            if (diag) {
                if (col0 + k     > row0 + m) w0 = 0.0f;
                if (col0 + k + 1 > row0 + m) w1 = 0.0f;
            }
            __half h0, l0, h1, l1;
            split1(w0, h0, l0);
            split1(w1, h1, l1);
            hv[j] = (uint32_t)__half_as_ushort(h0) | ((uint32_t)__half_as_ushort(h1) << 16);
            lv[j] = (uint32_t)__half_as_ushort(l0) | ((uint32_t)__half_as_ushort(l1) << 16);
        }
        *(uint4*)((uint32_t*)g_Sh + Rg * 128 + lane * 4) = make_uint4(hv[0], hv[1], hv[2], hv[3]);
        *(uint4*)((uint32_t*)g_Sl + Rg * 128 + lane * 4) = make_uint4(lv[0], lv[1], lv[2], lv[3]);
    }
}

// ===========================================================================
// O = S_w * V, 2-pass, k clamped to causal extent. grid (8, 16, 4)
// ===========================================================================
__global__ void __launch_bounds__(256, 2) k_pv(float* __restrict__ out)
{
    const int b    = blockIdx.z;
    const int row0 = b * TT + blockIdx.y * 128;
    const int col0 = blockIdx.x * 128;
    ACC_DECL;
    mma_core<2>(g_Sh, g_Sl, row0, TT >> 4,
                g_Vh + (size_t)b * TT * DD / 2, g_Vl + (size_t)b * TT * DD / 2,
                col0, TT >> 4, ((int)blockIdx.y + 1) * 4, acc);

    float* C = out + (size_t)b * TT * DD;
    const int lane = threadIdx.x & 31;
    const int wm   = (threadIdx.x >> 5) & 1;
    const int wn   = threadIdx.x >> 6;
    const int mb   = blockIdx.y * 128 + wm * 64 + (lane >> 2);
    const int nb   = col0 + wn * 32 + (lane & 3) * 2;
#pragma unroll
    for (int f = 0; f < 4; f++)
#pragma unroll
        for (int g = 0; g < 4; g++)
#pragma unroll
            for (int r = 0; r < 4; r++) {
                int M = mb + f * 16 + ((r >> 1) << 3);
                int N = nb + g * 8 + (r & 1);
                C[(size_t)M * DD + N] = acc[f][g][r];
            }
}

// ===========================================================================
extern "C" void kernel_launch(void* const* d_in, const int* in_sizes, int n_in,
                              void* d_out, int out_size)
{
    const float* X  = (const float*)d_in[0];
    const float* Wq = (const float*)d_in[1];
    const float* Wk = (const float*)d_in[2];
    const float* Wv = (const float*)d_in[3];
    float* out = (float*)d_out;

    const int SMEMB = 98304;                       // 3 x 32KB mma buffers
    const int WSMEM = (128 * 132 + 256) * 4;       // 68,608 B
    cudaFuncSetAttribute(k_gemmM, cudaFuncAttributeMaxDynamicSharedMemorySize, SMEMB);
    cudaFuncSetAttribute(k_xm,    cudaFuncAttributeMaxDynamicSharedMemorySize, SMEMB);
    cudaFuncSetAttribute(k_projV, cudaFuncAttributeMaxDynamicSharedMemorySize, SMEMB);
    cudaFuncSetAttribute(k_scores,cudaFuncAttributeMaxDynamicSharedMemorySize, SMEMB);
    cudaFuncSetAttribute(k_pv,    cudaFuncAttributeMaxDynamicSharedMemorySize, SMEMB);
    cudaFuncSetAttribute(k_wsplit,cudaFuncAttributeMaxDynamicSharedMemorySize, WSMEM);

    k_splitX <<<(BB * TT * DD) / 1024, 256>>>(X);
    k_splitWq<<<(DD * DD) / 1024, 256>>>(Wq);
    k_splitWk<<<(DD * DD) / 1024, 256>>>(Wk);
    k_splitWv<<<(DD * DD) / 512, 256>>>(Wv);
    k_gemmM  <<<dim3(DD / 128, DD / 128), 256, SMEMB>>>();
    k_projV  <<<dim3(DD / 128, (BB * TT) / 128), 256, SMEMB>>>();
    k_xm     <<<dim3(DD / 128, (BB * TT) / 128), 256, SMEMB>>>();
    k_scores <<<dim3(TT / 128, TT / 128, BB), 256, SMEMB>>>();
    k_rowstat<<<BB * TT, 256>>>();
    k_wsplit <<<dim3(TT / 128, TT / 128, BB), 256, WSMEM>>>();
    k_pv     <<<dim3(DD / 128, TT / 128, BB), 256, SMEMB>>>(out);
}

// round 14
// speedup vs baseline: 4.0205x; 1.1524x over previous
#include <cuda_runtime.h>
#include <cuda_fp16.h>
#include <math_constants.h>
#include <cstdint>

#define BB 4
#define TT 2048
#define DD 1024

// ============ scratch: fp16 hi/lo split arrays in mma fragment order =======
__device__ __half2 g_Xh [(size_t)BB * TT * DD / 2];   // X, A-layout
__device__ __half2 g_Xl [(size_t)BB * TT * DD / 2];
__device__ __half2 g_XBh[(size_t)BB * TT * DD / 2];   // X, B-layout
__device__ __half2 g_XBl[(size_t)BB * TT * DD / 2];
__device__ __half2 g_WqA[(size_t)DD * DD / 2];
__device__ __half2 g_WqAl[(size_t)DD * DD / 2];
__device__ __half2 g_WkB[(size_t)DD * DD / 2];
__device__ __half2 g_WkBl[(size_t)DD * DD / 2];
__device__ __half2 g_WvB[(size_t)DD * DD / 2];
__device__ __half2 g_WvBl[(size_t)DD * DD / 2];
__device__ __half2 g_Mh [(size_t)DD * DD / 2];        // M = Wq Wk^T, B-layout
__device__ __half2 g_Ml [(size_t)DD * DD / 2];
__device__ __half2 g_XMh[(size_t)BB * TT * DD / 2];   // XM, A-layout
__device__ __half2 g_XMl[(size_t)BB * TT * DD / 2];
__device__ __half2 g_Vh [(size_t)BB * TT * DD / 2];   // V, B-layout per batch
__device__ __half2 g_Vl [(size_t)BB * TT * DD / 2];
__device__ float   g_S  [(size_t)BB * TT * TT];
__device__ __half2 g_Sh [(size_t)BB * TT * TT / 2];
__device__ __half2 g_Sl [(size_t)BB * TT * TT / 2];
__device__ float   g_rowM[(size_t)BB * TT];
__device__ float   g_rowI[(size_t)BB * TT];

// ============================ helpers ======================================
__device__ __forceinline__ uint32_t smem_to_u32(const void* p) {
    uint32_t a;
    asm("{ .reg .u64 t; cvta.to.shared.u64 t, %1; cvt.u32.u64 %0, t; }"
        : "=r"(a) : "l"(p));
    return a;
}

__device__ __forceinline__ void mma16(float* d, uint4 a, uint2 b) {
    asm volatile(
        "mma.sync.aligned.m16n8k16.row.col.f32.f16.f16.f32 "
        "{%0,%1,%2,%3}, {%4,%5,%6,%7}, {%8,%9}, {%0,%1,%2,%3};"
        : "+f"(d[0]), "+f"(d[1]), "+f"(d[2]), "+f"(d[3])
        : "r"(a.x), "r"(a.y), "r"(a.z), "r"(a.w), "r"(b.x), "r"(b.y));
}

__device__ __forceinline__ size_t idxA32(int m, int k, int Kt) {
    return ((size_t)((m >> 4) * (Kt >> 4) + (k >> 4))) * 128
         + (size_t)((((m & 7) * 4 + ((k & 7) >> 1)) * 4)
                    + ((m >> 3) & 1) + (((k >> 3) & 1) << 1));
}
__device__ __forceinline__ size_t idxB32(int k, int n, int Kt) {
    return ((size_t)((n >> 3) * (Kt >> 4) + (k >> 4))) * 64
         + (size_t)((((n & 7) * 4 + ((k & 7) >> 1)) * 2) + ((k >> 3) & 1));
}

__device__ __forceinline__ void split1(float x, __half& h, __half& l) {
    h = __float2half_rn(x);
    l = __float2half_rn(x - __half2float(h));
}
__device__ __forceinline__ void wsplitA_pair(
    __half2* H, __half2* L, int m, int k, int Kt, float x0, float x1)
{
    __half h0, l0, h1, l1;
    split1(x0, h0, l0); split1(x1, h1, l1);
    size_t i = idxA32(m, k, Kt);
    H[i] = __halves2half2(h0, h1);
    L[i] = __halves2half2(l0, l1);
}
__device__ __forceinline__ void wsplitB_pair(
    __half2* H, __half2* L, int k, int n, int Kt, float x0, float x1)
{
    __half h0, l0, h1, l1;
    split1(x0, h0, l0); split1(x1, h1, l1);
    size_t i = idxB32(k, n, Kt);
    H[i] = __halves2half2(h0, h1);
    L[i] = __halves2half2(l0, l1);
}
__device__ __forceinline__ void wsplitB_half(
    __half2* H, __half2* L, int k, int n, int Kt, float x)
{
    __half h, l;
    split1(x, h, l);
    size_t i = idxB32(k, n, Kt) * 2 + (size_t)(k & 1);
    ((__half*)H)[i] = h;
    ((__half*)L)[i] = l;
}

__device__ __forceinline__ void cpasync16(uint32_t dst, const void* src) {
    asm volatile("cp.async.cg.shared.global [%0], [%1], 16;" :: "r"(dst), "l"(src));
}

// lower-triangular tile decode: t -> (by, bx), t = by*(by+1)/2 + bx, bx<=by
__device__ __forceinline__ void tri_decode(int t, int& by, int& bx) {
    int y = (int)((sqrtf(8.0f * (float)t + 1.0f) - 1.0f) * 0.5f);
    while ((y + 1) * (y + 2) / 2 <= t) y++;
    while (y * (y + 1) / 2 > t) y--;
    by = y;
    bx = t - y * (y + 1) / 2;
}

// ===========================================================================
// MMA core (unchanged engine)
// ===========================================================================
template<int NPASS>
__device__ __forceinline__ void mma_core(
    const __half2* __restrict__ Ah, const __half2* __restrict__ Al,
    int row0A, int aKt,
    const __half2* __restrict__ Bh, const __half2* __restrict__ Bl,
    int col0B, int bKt,
    int nchunks, float acc[4][4][4])
{
    extern __shared__ char smem[];
    const int tid  = threadIdx.x;
    const int lane = tid & 31;
    const int wm   = (tid >> 5) & 1;
    const int wn   = tid >> 6;
    const uint32_t sb_u32 = smem_to_u32(smem);

    const int aRB0 = (row0A >> 4) * aKt;
    const int bRB0 = (col0B >> 3) * bKt;

    auto copy_chunk = [&](int chunk) {
        const uint32_t sbase = sb_u32 + (uint32_t)(chunk % 3) * 32768u;
        for (int c = tid; c < 512; c += 256) {
            int rr = c >> 5;
            size_t off = (size_t)(aRB0 + (rr >> 1) * aKt + chunk * 2 + (rr & 1)) * 128
                       + (size_t)((c & 31) << 2);
            uint32_t d = sbase + (uint32_t)(c << 4);
            cpasync16(d,         Ah + off);
            cpasync16(d + 8192u, Al + off);
        }
        for (int c = tid; c < 512; c += 256) {
            int rr = c >> 4;
            size_t off = (size_t)(bRB0 + (rr >> 1) * bKt + chunk * 2 + (rr & 1)) * 64
                       + (size_t)((c & 15) << 2);
            uint32_t d = sbase + 16384u + (uint32_t)(c << 4);
            cpasync16(d,         Bh + off);
            cpasync16(d + 8192u, Bl + off);
        }
        asm volatile("cp.async.commit_group;");
    };

    copy_chunk(0);
    if (nchunks > 1) copy_chunk(1);

    for (int t = 0; t < nchunks; t++) {
        if (t + 1 < nchunks) asm volatile("cp.async.wait_group 1;");
        else                 asm volatile("cp.async.wait_group 0;");
        __syncthreads();

        if (t + 2 < nchunks) copy_chunk(t + 2);

        const char* sb = smem + (size_t)(t % 3) * 32768;
        const uint4* pAh = (const uint4*)sb;
        const uint4* pAl = (const uint4*)(sb + 8192);
        const uint2* pBh = (const uint2*)(sb + 16384);
        const uint2* pBl = (const uint2*)(sb + 24576);

#pragma unroll
        for (int ki = 0; ki < 2; ki++) {
            uint4 fAh[4]; uint2 fBh[4];
#pragma unroll
            for (int f = 0; f < 4; f++)
                fAh[f] = pAh[((wm * 4 + f) * 2 + ki) * 32 + lane];
#pragma unroll
            for (int g = 0; g < 4; g++)
                fBh[g] = pBh[((wn * 4 + g) * 2 + ki) * 32 + lane];
#pragma unroll
            for (int f = 0; f < 4; f++)
#pragma unroll
                for (int g = 0; g < 4; g++) mma16(acc[f][g], fAh[f], fBh[g]);
            {
                uint4 fAl[4];
#pragma unroll
                for (int f = 0; f < 4; f++)
                    fAl[f] = pAl[((wm * 4 + f) * 2 + ki) * 32 + lane];
#pragma unroll
                for (int f = 0; f < 4; f++)
#pragma unroll
                    for (int g = 0; g < 4; g++) mma16(acc[f][g], fAl[f], fBh[g]);
            }
            if (NPASS == 3) {
                uint2 fBl[4];
#pragma unroll
                for (int g = 0; g < 4; g++)
                    fBl[g] = pBl[((wn * 4 + g) * 2 + ki) * 32 + lane];
#pragma unroll
                for (int f = 0; f < 4; f++)
#pragma unroll
                    for (int g = 0; g < 4; g++) mma16(acc[f][g], fAh[f], fBl[g]);
            }
        }
    }
    __syncthreads();
}
// acc coords: m = wm*64 + f*16 + (lane>>2) + 8*(r>>1); n = wn*32 + g*8 + (lane&3)*2 + (r&1)

#define ACC_DECL float acc[4][4][4]; \
    _Pragma("unroll") for (int f = 0; f < 4; f++) \
    _Pragma("unroll") for (int g = 0; g < 4; g++) \
    _Pragma("unroll") for (int r = 0; r < 4; r++) acc[f][g][r] = 0.0f;

// ===========================================================================
// Merged splits: one launch.
//   blocks [0, 8192)       : X  -> A-layout + B-layout
//   blocks [8192, 9216)    : Wq -> A-layout
//   blocks [9216, 10240)   : Wk -> B-layout
//   blocks [10240, 12288)  : Wv -> B-layout (pair-of-rows form)
// ===========================================================================
__global__ void __launch_bounds__(256) k_split(
    const float* __restrict__ X,  const float* __restrict__ Wq,
    const float* __restrict__ Wk, const float* __restrict__ Wv)
{
    const int bid = blockIdx.x;
    const int tid = threadIdx.x;
    if (bid < 8192) {
        int i = bid * 256 + tid;
        int m  = i >> 8;
        int d0 = (i & 255) << 2;
        float4 v = *(const float4*)(X + (size_t)m * DD + d0);
        wsplitA_pair(g_Xh,  g_Xl,  m, d0,     DD, v.x, v.y);
        wsplitA_pair(g_Xh,  g_Xl,  m, d0 + 2, DD, v.z, v.w);
        wsplitB_pair(g_XBh, g_XBl, d0,     m, DD, v.x, v.y);
        wsplitB_pair(g_XBh, g_XBl, d0 + 2, m, DD, v.z, v.w);
    } else if (bid < 9216) {
        int i = (bid - 8192) * 256 + tid;
        int d  = i >> 8;
        int j0 = (i & 255) << 2;
        float4 v = *(const float4*)(Wq + (size_t)d * DD + j0);
        wsplitA_pair(g_WqA, g_WqAl, d, j0,     DD, v.x, v.y);
        wsplitA_pair(g_WqA, g_WqAl, d, j0 + 2, DD, v.z, v.w);
    } else if (bid < 10240) {
        int i = (bid - 9216) * 256 + tid;
        int e  = i >> 8;
        int j0 = (i & 255) << 2;
        float4 v = *(const float4*)(Wk + (size_t)e * DD + j0);
        wsplitB_pair(g_WkB, g_WkBl, j0,     e, DD, v.x, v.y);
        wsplitB_pair(g_WkB, g_WkBl, j0 + 2, e, DD, v.z, v.w);
    } else {
        int i = (bid - 10240) * 256 + tid;
        int r2 = (i >> 10) << 1;
        int c  = i & 1023;
        float x0 = Wv[(size_t)r2 * DD + c];
        float x1 = Wv[(size_t)(r2 + 1) * DD + c];
        wsplitB_pair(g_WvB, g_WvBl, r2, c, DD, x0, x1);
    }
}

// ===========================================================================
// M = Wq @ Wk^T. grid (8, 8). 3-pass (precision-critical).
// ===========================================================================
__global__ void __launch_bounds__(256, 2) k_gemmM()
{
    const int row0 = blockIdx.y * 128;
    const int col0 = blockIdx.x * 128;
    ACC_DECL;
    mma_core<3>(g_WqA, g_WqAl, row0, DD >> 4,
                g_WkB, g_WkBl, col0, DD >> 4, DD >> 5, acc);

    const int lane = threadIdx.x & 31;
    const int wm   = (threadIdx.x >> 5) & 1;
    const int wn   = threadIdx.x >> 6;
    const int mb   = row0 + wm * 64 + (lane >> 2);
    const int nb   = col0 + wn * 32 + (lane & 3) * 2;
#pragma unroll
    for (int f = 0; f < 4; f++)
#pragma unroll
        for (int g = 0; g < 4; g++)
#pragma unroll
            for (int r = 0; r < 4; r++) {
                int Md = mb + f * 16 + ((r >> 1) << 3);
                int Ne = nb + g * 8 + (r & 1);
                wsplitB_half(g_Mh, g_Ml, Md, Ne, DD, acc[f][g][r]);
            }
}

// ===========================================================================
// Merged XM (z=0, 3-pass) + V projection (z=1, 2-pass). grid (8, 64, 2).
// ===========================================================================
__global__ void __launch_bounds__(256, 2) k_xmv()
{
    const int row0 = blockIdx.y * 128;
    const int col0 = blockIdx.x * 128;
    const int lane = threadIdx.x & 31;
    const int wm   = (threadIdx.x >> 5) & 1;
    const int wn   = threadIdx.x >> 6;
    const int mb   = row0 + wm * 64 + (lane >> 2);
    const int nb   = col0 + wn * 32 + (lane & 3) * 2;

    if (blockIdx.z == 0) {
        ACC_DECL;
        mma_core<3>(g_Xh, g_Xl, row0, DD >> 4,
                    g_Mh, g_Ml, col0, DD >> 4, DD >> 5, acc);
#pragma unroll
        for (int f = 0; f < 4; f++)
#pragma unroll
            for (int g = 0; g < 4; g++) {
                int M0 = mb + f * 16;
                int N  = nb + g * 8;
                wsplitA_pair(g_XMh, g_XMl, M0,     N, DD, acc[f][g][0], acc[f][g][1]);
                wsplitA_pair(g_XMh, g_XMl, M0 + 8, N, DD, acc[f][g][2], acc[f][g][3]);
            }
    } else {
        ACC_DECL;
        mma_core<2>(g_Xh, g_Xl, row0, DD >> 4,
                    g_WvB, g_WvBl, col0, DD >> 4, DD >> 5, acc);
#pragma unroll
        for (int f = 0; f < 4; f++)
#pragma unroll
            for (int g = 0; g < 4; g++)
#pragma unroll
                for (int r = 0; r < 4; r++) {
                    int Mg = mb + f * 16 + ((r >> 1) << 3);
                    int b  = Mg >> 11;
                    int sl = Mg & (TT - 1);
                    wsplitB_half(g_Vh + (size_t)b * TT * DD / 2,
                                 g_Vl + (size_t)b * TT * DD / 2,
                                 sl, nb + g * 8 + (r & 1), TT, acc[f][g][r]);
                }
    }
}

// ===========================================================================
// Scores S = (XM @ X^T)/32. Exact lower-tri 1D grid: 136 tiles x 4 batches.
// ===========================================================================
__global__ void __launch_bounds__(256, 2) k_scores()
{
    const int b = blockIdx.x / 136;
    int by, bx;
    tri_decode(blockIdx.x % 136, by, bx);
    const int row0 = b * TT + by * 128;
    const int col0 = b * TT + bx * 128;
    ACC_DECL;
    mma_core<3>(g_XMh, g_XMl, row0, DD >> 4,
                g_XBh, g_XBl, col0, DD >> 4, DD >> 5, acc);

    float* C = g_S + (size_t)b * TT * TT;
    const int lane = threadIdx.x & 31;
    const int wm   = (threadIdx.x >> 5) & 1;
    const int wn   = threadIdx.x >> 6;
    const int mb   = by * 128 + wm * 64 + (lane >> 2);
    const int nb   = bx * 128 + wn * 32 + (lane & 3) * 2;
#pragma unroll
    for (int f = 0; f < 4; f++)
#pragma unroll
        for (int g = 0; g < 4; g++)
#pragma unroll
            for (int r = 0; r < 4; r++) {
                int M = mb + f * 16 + ((r >> 1) << 3);
                int N = nb + g * 8 + (r & 1);
                C[(size_t)M * TT + N] = acc[f][g][r] * 0.03125f;
            }
}

// ===========================================================================
// Phase 1 softmax: per-row max and 1/sum. grid = B*T, 256 thr.
// ===========================================================================
__global__ void __launch_bounds__(256) k_rowstat()
{
    const int row = blockIdx.x;
    const int i   = row & (TT - 1);
    const float* s = g_S + (size_t)row * TT;
    const int L = i + 1;
    const int tid = threadIdx.x;
    __shared__ float red[256];

    float m = -CUDART_INF_F;
    for (int j = tid; j < L; j += 256) m = fmaxf(m, s[j]);
    red[tid] = m;
    __syncthreads();
    for (int w = 128; w > 0; w >>= 1) {
        if (tid < w) red[tid] = fmaxf(red[tid], red[tid + w]);
        __syncthreads();
    }
    m = red[0];
    __syncthreads();

    float sum = 0.0f;
    for (int j = tid; j < L; j += 256) sum += __expf(s[j] - m);
    red[tid] = sum;
    __syncthreads();
    for (int w = 128; w > 0; w >>= 1) {
        if (tid < w) red[tid] += red[tid + w];
        __syncthreads();
    }
    if (tid == 0) {
        g_rowM[row] = m;
        g_rowI[row] = 1.0f / red[0];
    }
}

// ===========================================================================
// Phase 2 softmax: exact lower-tri grid; coalesced A-layout region stores.
// ===========================================================================
__global__ void __launch_bounds__(256) k_wsplit()
{
    extern __shared__ float sws[];
    float* sS = sws;                    // 128 * 132
    float* sM = sws + 128 * 132;        // 128
    float* sI = sM + 128;               // 128

    const int b = blockIdx.x / 136;
    int by, bx;
    tri_decode(blockIdx.x % 136, by, bx);
    const int tid = threadIdx.x;
    const int row0 = by * 128;
    const int col0 = bx * 128;
    const float* S = g_S + (size_t)b * TT * TT;

    for (int i = tid; i < 4096; i += 256) {
        int r  = i >> 5;
        int c4 = (i & 31) << 2;
        float4 v = *(const float4*)(S + (size_t)(row0 + r) * TT + col0 + c4);
        sS[r * 132 + c4 + 0] = v.x;
        sS[r * 132 + c4 + 1] = v.y;
        sS[r * 132 + c4 + 2] = v.z;
        sS[r * 132 + c4 + 3] = v.w;
    }
    if (tid < 128) {
        sM[tid] = g_rowM[b * TT + row0 + tid];
        sI[tid] = g_rowI[b * TT + row0 + tid];
    }
    __syncthreads();

    const int w    = tid >> 5;
    const int lane = tid & 31;
    const bool diag = (bx == by);

    for (int kreg = 0; kreg < 8; kreg++) {
        const size_t Rg = ((size_t)(b * 128 + by * 8 + w)) * 128 + (size_t)(bx * 8 + kreg);
        uint32_t hv[4], lv[4];
#pragma unroll
        for (int j = 0; j < 4; j++) {
            int m = w * 16 + (lane >> 2) + 8 * (j & 1);
            int k = kreg * 16 + (lane & 3) * 2 + 8 * ((j >> 1) & 1);
            float mx  = sM[m];
            float inv = sI[m];
            float w0 = __expf(sS[m * 132 + k]     - mx) * inv;
            float w1 = __expf(sS[m * 132 + k + 1] - mx) * inv;
            if (diag) {
                if (col0 + k     > row0 + m) w0 = 0.0f;
                if (col0 + k + 1 > row0 + m) w1 = 0.0f;
            }
            __half h0, l0, h1, l1;
            split1(w0, h0, l0);
            split1(w1, h1, l1);
            hv[j] = (uint32_t)__half_as_ushort(h0) | ((uint32_t)__half_as_ushort(h1) << 16);
            lv[j] = (uint32_t)__half_as_ushort(l0) | ((uint32_t)__half_as_ushort(l1) << 16);
        }
        *(uint4*)((uint32_t*)g_Sh + Rg * 128 + lane * 4) = make_uint4(hv[0], hv[1], hv[2], hv[3]);
        *(uint4*)((uint32_t*)g_Sl + Rg * 128 + lane * 4) = make_uint4(lv[0], lv[1], lv[2], lv[3]);
    }
}

// ===========================================================================
// O = S_w * V, 2-pass, k clamped. Longest-first ordering (by reversed).
// ===========================================================================
__global__ void __launch_bounds__(256, 2) k_pv(float* __restrict__ out)
{
    const int b    = blockIdx.z;
    const int by   = 15 - (int)blockIdx.y;     // heavy CTAs scheduled first
    const int row0 = b * TT + by * 128;
    const int col0 = blockIdx.x * 128;
    ACC_DECL;
    mma_core<2>(g_Sh, g_Sl, row0, TT >> 4,
                g_Vh + (size_t)b * TT * DD / 2, g_Vl + (size_t)b * TT * DD / 2,
                col0, TT >> 4, (by + 1) * 4, acc);

    float* C = out + (size_t)b * TT * DD;
    const int lane = threadIdx.x & 31;
    const int wm   = (threadIdx.x >> 5) & 1;
    const int wn   = threadIdx.x >> 6;
    const int mb   = by * 128 + wm * 64 + (lane >> 2);
    const int nb   = col0 + wn * 32 + (lane & 3) * 2;
#pragma unroll
    for (int f = 0; f < 4; f++)
#pragma unroll
        for (int g = 0; g < 4; g++)
#pragma unroll
            for (int r = 0; r < 4; r++) {
                int M = mb + f * 16 + ((r >> 1) << 3);
                int N = nb + g * 8 + (r & 1);
                C[(size_t)M * DD + N] = acc[f][g][r];
            }
}

// ===========================================================================
extern "C" void kernel_launch(void* const* d_in, const int* in_sizes, int n_in,
                              void* d_out, int out_size)
{
    const float* X  = (const float*)d_in[0];
    const float* Wq = (const float*)d_in[1];
    const float* Wk = (const float*)d_in[2];
    const float* Wv = (const float*)d_in[3];
    float* out = (float*)d_out;

    const int SMEMB = 98304;                       // 3 x 32KB mma buffers
    const int WSMEM = (128 * 132 + 256) * 4;       // 68,608 B
    cudaFuncSetAttribute(k_gemmM, cudaFuncAttributeMaxDynamicSharedMemorySize, SMEMB);
    cudaFuncSetAttribute(k_xmv,   cudaFuncAttributeMaxDynamicSharedMemorySize, SMEMB);
    cudaFuncSetAttribute(k_scores,cudaFuncAttributeMaxDynamicSharedMemorySize, SMEMB);
    cudaFuncSetAttribute(k_pv,    cudaFuncAttributeMaxDynamicSharedMemorySize, SMEMB);
    cudaFuncSetAttribute(k_wsplit,cudaFuncAttributeMaxDynamicSharedMemorySize, WSMEM);

    k_split  <<<12288, 256>>>(X, Wq, Wk, Wv);
    k_gemmM  <<<dim3(DD / 128, DD / 128), 256, SMEMB>>>();
    k_xmv    <<<dim3(DD / 128, (BB * TT) / 128, 2), 256, SMEMB>>>();
    k_scores <<<136 * BB, 256, SMEMB>>>();
    k_rowstat<<<BB * TT, 256>>>();
    k_wsplit <<<136 * BB, 256, WSMEM>>>();
    k_pv     <<<dim3(DD / 128, TT / 128, BB), 256, SMEMB>>>(out);
}

// round 15
// speedup vs baseline: 4.4367x; 1.1035x over previous
#include <cuda_runtime.h>
#include <cuda_fp16.h>
#include <math_constants.h>
#include <cstdint>

#define BB 4
#define TT 2048
#define DD 1024

// ============ scratch: fp16 hi/lo split arrays in mma fragment order =======
__device__ __half2 g_Xh [(size_t)BB * TT * DD / 2];   // X, A-layout
__device__ __half2 g_Xl [(size_t)BB * TT * DD / 2];
__device__ __half2 g_XBh[(size_t)BB * TT * DD / 2];   // X, B-layout
__device__ __half2 g_XBl[(size_t)BB * TT * DD / 2];
__device__ __half2 g_WqA[(size_t)DD * DD / 2];
__device__ __half2 g_WqAl[(size_t)DD * DD / 2];
__device__ __half2 g_WkB[(size_t)DD * DD / 2];
__device__ __half2 g_WkBl[(size_t)DD * DD / 2];
__device__ __half2 g_WvB[(size_t)DD * DD / 2];        // h only (pv uses Vh only)
__device__ __half2 g_Mh [(size_t)DD * DD / 2];        // M = Wq Wk^T, B-layout
__device__ __half2 g_Ml [(size_t)DD * DD / 2];
__device__ __half2 g_XMh[(size_t)BB * TT * DD / 2];   // XM, A-layout
__device__ __half2 g_XMl[(size_t)BB * TT * DD / 2];
__device__ __half2 g_Vh [(size_t)BB * TT * DD / 2];   // V, B-layout per batch (h only)
__device__ float   g_S  [(size_t)BB * TT * TT];
__device__ __half2 g_Sh [(size_t)BB * TT * TT / 2];   // softmax weights, h only
__device__ float   g_rowM[(size_t)BB * TT];
__device__ float   g_rowI[(size_t)BB * TT];

// ============================ helpers ======================================
__device__ __forceinline__ uint32_t smem_to_u32(const void* p) {
    uint32_t a;
    asm("{ .reg .u64 t; cvta.to.shared.u64 t, %1; cvt.u32.u64 %0, t; }"
        : "=r"(a) : "l"(p));
    return a;
}

__device__ __forceinline__ void mma16(float* d, uint4 a, uint2 b) {
    asm volatile(
        "mma.sync.aligned.m16n8k16.row.col.f32.f16.f16.f32 "
        "{%0,%1,%2,%3}, {%4,%5,%6,%7}, {%8,%9}, {%0,%1,%2,%3};"
        : "+f"(d[0]), "+f"(d[1]), "+f"(d[2]), "+f"(d[3])
        : "r"(a.x), "r"(a.y), "r"(a.z), "r"(a.w), "r"(b.x), "r"(b.y));
}

__device__ __forceinline__ size_t idxA32(int m, int k, int Kt) {
    return ((size_t)((m >> 4) * (Kt >> 4) + (k >> 4))) * 128
         + (size_t)((((m & 7) * 4 + ((k & 7) >> 1)) * 4)
                    + ((m >> 3) & 1) + (((k >> 3) & 1) << 1));
}
__device__ __forceinline__ size_t idxB32(int k, int n, int Kt) {
    return ((size_t)((n >> 3) * (Kt >> 4) + (k >> 4))) * 64
         + (size_t)((((n & 7) * 4 + ((k & 7) >> 1)) * 2) + ((k >> 3) & 1));
}

__device__ __forceinline__ void split1(float x, __half& h, __half& l) {
    h = __float2half_rn(x);
    l = __float2half_rn(x - __half2float(h));
}
__device__ __forceinline__ void wsplitA_pair(
    __half2* H, __half2* L, int m, int k, int Kt, float x0, float x1)
{
    __half h0, l0, h1, l1;
    split1(x0, h0, l0); split1(x1, h1, l1);
    size_t i = idxA32(m, k, Kt);
    H[i] = __halves2half2(h0, h1);
    L[i] = __halves2half2(l0, l1);
}
__device__ __forceinline__ void wsplitB_pair(
    __half2* H, __half2* L, int k, int n, int Kt, float x0, float x1)
{
    __half h0, l0, h1, l1;
    split1(x0, h0, l0); split1(x1, h1, l1);
    size_t i = idxB32(k, n, Kt);
    H[i] = __halves2half2(h0, h1);
    L[i] = __halves2half2(l0, l1);
}
// h-only variants (consumer never reads the low part)
__device__ __forceinline__ void wB_pair_h(
    __half2* H, int k, int n, int Kt, float x0, float x1)
{
    H[idxB32(k, n, Kt)] =
        __halves2half2(__float2half_rn(x0), __float2half_rn(x1));
}
__device__ __forceinline__ void wB_half_h(
    __half2* H, int k, int n, int Kt, float x)
{
    size_t i = idxB32(k, n, Kt) * 2 + (size_t)(k & 1);
    ((__half*)H)[i] = __float2half_rn(x);
}
__device__ __forceinline__ void wsplitB_half(
    __half2* H, __half2* L, int k, int n, int Kt, float x)
{
    __half h, l;
    split1(x, h, l);
    size_t i = idxB32(k, n, Kt) * 2 + (size_t)(k & 1);
    ((__half*)H)[i] = h;
    ((__half*)L)[i] = l;
}

__device__ __forceinline__ void cpasync16(uint32_t dst, const void* src) {
    asm volatile("cp.async.cg.shared.global [%0], [%1], 16;" :: "r"(dst), "l"(src));
}

// lower-triangular tile decode: t -> (by, bx), t = by*(by+1)/2 + bx, bx<=by
__device__ __forceinline__ void tri_decode(int t, int& by, int& bx) {
    int y = (int)((sqrtf(8.0f * (float)t + 1.0f) - 1.0f) * 0.5f);
    while ((y + 1) * (y + 2) / 2 <= t) y++;
    while (y * (y + 1) / 2 > t) y--;
    by = y;
    bx = t - y * (y + 1) / 2;
}

// ===========================================================================
// MMA core. NPASS=3: hh+lh+hl; NPASS=2: hh+lh; NPASS=1: hh.
// cp.async of Al only when NPASS>=2; of Bl only when NPASS==3.
// 3-stage pipeline, one barrier per chunk. smem layout fixed (32KB/buffer).
// ===========================================================================
template<int NPASS>
__device__ __forceinline__ void mma_core(
    const __half2* __restrict__ Ah, const __half2* __restrict__ Al,
    int row0A, int aKt,
    const __half2* __restrict__ Bh, const __half2* __restrict__ Bl,
    int col0B, int bKt,
    int nchunks, float acc[4][4][4])
{
    extern __shared__ char smem[];
    const int tid  = threadIdx.x;
    const int lane = tid & 31;
    const int wm   = (tid >> 5) & 1;
    const int wn   = tid >> 6;
    const uint32_t sb_u32 = smem_to_u32(smem);

    const int aRB0 = (row0A >> 4) * aKt;
    const int bRB0 = (col0B >> 3) * bKt;

    auto copy_chunk = [&](int chunk) {
        const uint32_t sbase = sb_u32 + (uint32_t)(chunk % 3) * 32768u;
        for (int c = tid; c < 512; c += 256) {
            int rr = c >> 5;
            size_t off = (size_t)(aRB0 + (rr >> 1) * aKt + chunk * 2 + (rr & 1)) * 128
                       + (size_t)((c & 31) << 2);
            uint32_t d = sbase + (uint32_t)(c << 4);
            cpasync16(d, Ah + off);
            if (NPASS >= 2) cpasync16(d + 8192u, Al + off);
        }
        for (int c = tid; c < 512; c += 256) {
            int rr = c >> 4;
            size_t off = (size_t)(bRB0 + (rr >> 1) * bKt + chunk * 2 + (rr & 1)) * 64
                       + (size_t)((c & 15) << 2);
            uint32_t d = sbase + 16384u + (uint32_t)(c << 4);
            cpasync16(d, Bh + off);
            if (NPASS == 3) cpasync16(d + 8192u, Bl + off);
        }
        asm volatile("cp.async.commit_group;");
    };

    copy_chunk(0);
    if (nchunks > 1) copy_chunk(1);

    for (int t = 0; t < nchunks; t++) {
        if (t + 1 < nchunks) asm volatile("cp.async.wait_group 1;");
        else                 asm volatile("cp.async.wait_group 0;");
        __syncthreads();

        if (t + 2 < nchunks) copy_chunk(t + 2);

        const char* sb = smem + (size_t)(t % 3) * 32768;
        const uint4* pAh = (const uint4*)sb;
        const uint4* pAl = (const uint4*)(sb + 8192);
        const uint2* pBh = (const uint2*)(sb + 16384);
        const uint2* pBl = (const uint2*)(sb + 24576);

#pragma unroll
        for (int ki = 0; ki < 2; ki++) {
            uint4 fAh[4]; uint2 fBh[4];
#pragma unroll
            for (int f = 0; f < 4; f++)
                fAh[f] = pAh[((wm * 4 + f) * 2 + ki) * 32 + lane];
#pragma unroll
            for (int g = 0; g < 4; g++)
                fBh[g] = pBh[((wn * 4 + g) * 2 + ki) * 32 + lane];
#pragma unroll
            for (int f = 0; f < 4; f++)
#pragma unroll
                for (int g = 0; g < 4; g++) mma16(acc[f][g], fAh[f], fBh[g]);
            if (NPASS >= 2) {
                uint4 fAl[4];
#pragma unroll
                for (int f = 0; f < 4; f++)
                    fAl[f] = pAl[((wm * 4 + f) * 2 + ki) * 32 + lane];
#pragma unroll
                for (int f = 0; f < 4; f++)
#pragma unroll
                    for (int g = 0; g < 4; g++) mma16(acc[f][g], fAl[f], fBh[g]);
            }
            if (NPASS == 3) {
                uint2 fBl[4];
#pragma unroll
                for (int g = 0; g < 4; g++)
                    fBl[g] = pBl[((wn * 4 + g) * 2 + ki) * 32 + lane];
#pragma unroll
                for (int f = 0; f < 4; f++)
#pragma unroll
                    for (int g = 0; g < 4; g++) mma16(acc[f][g], fAh[f], fBl[g]);
            }
        }
    }
    __syncthreads();
}
// acc coords: m = wm*64 + f*16 + (lane>>2) + 8*(r>>1); n = wn*32 + g*8 + (lane&3)*2 + (r&1)

#define ACC_DECL float acc[4][4][4]; \
    _Pragma("unroll") for (int f = 0; f < 4; f++) \
    _Pragma("unroll") for (int g = 0; g < 4; g++) \
    _Pragma("unroll") for (int r = 0; r < 4; r++) acc[f][g][r] = 0.0f;

// ===========================================================================
// Merged splits: one launch.
// ===========================================================================
__global__ void __launch_bounds__(256) k_split(
    const float* __restrict__ X,  const float* __restrict__ Wq,
    const float* __restrict__ Wk, const float* __restrict__ Wv)
{
    const int bid = blockIdx.x;
    const int tid = threadIdx.x;
    if (bid < 8192) {
        int i = bid * 256 + tid;
        int m  = i >> 8;
        int d0 = (i & 255) << 2;
        float4 v = *(const float4*)(X + (size_t)m * DD + d0);
        wsplitA_pair(g_Xh,  g_Xl,  m, d0,     DD, v.x, v.y);
        wsplitA_pair(g_Xh,  g_Xl,  m, d0 + 2, DD, v.z, v.w);
        wsplitB_pair(g_XBh, g_XBl, d0,     m, DD, v.x, v.y);
        wsplitB_pair(g_XBh, g_XBl, d0 + 2, m, DD, v.z, v.w);
    } else if (bid < 9216) {
        int i = (bid - 8192) * 256 + tid;
        int d  = i >> 8;
        int j0 = (i & 255) << 2;
        float4 v = *(const float4*)(Wq + (size_t)d * DD + j0);
        wsplitA_pair(g_WqA, g_WqAl, d, j0,     DD, v.x, v.y);
        wsplitA_pair(g_WqA, g_WqAl, d, j0 + 2, DD, v.z, v.w);
    } else if (bid < 10240) {
        int i = (bid - 9216) * 256 + tid;
        int e  = i >> 8;
        int j0 = (i & 255) << 2;
        float4 v = *(const float4*)(Wk + (size_t)e * DD + j0);
        wsplitB_pair(g_WkB, g_WkBl, j0,     e, DD, v.x, v.y);
        wsplitB_pair(g_WkB, g_WkBl, j0 + 2, e, DD, v.z, v.w);
    } else {
        int i = (bid - 10240) * 256 + tid;
        int r2 = (i >> 10) << 1;
        int c  = i & 1023;
        float x0 = Wv[(size_t)r2 * DD + c];
        float x1 = Wv[(size_t)(r2 + 1) * DD + c];
        wB_pair_h(g_WvB, r2, c, DD, x0, x1);   // h only: projV is 2-pass (Xh+Xl)*Wvh
    }
}

// ===========================================================================
// M = Wq @ Wk^T. grid (8, 8). 3-pass (precision-critical).
// ===========================================================================
__global__ void __launch_bounds__(256, 2) k_gemmM()
{
    const int row0 = blockIdx.y * 128;
    const int col0 = blockIdx.x * 128;
    ACC_DECL;
    mma_core<3>(g_WqA, g_WqAl, row0, DD >> 4,
                g_WkB, g_WkBl, col0, DD >> 4, DD >> 5, acc);

    const int lane = threadIdx.x & 31;
    const int wm   = (threadIdx.x >> 5) & 1;
    const int wn   = threadIdx.x >> 6;
    const int mb   = row0 + wm * 64 + (lane >> 2);
    const int nb   = col0 + wn * 32 + (lane & 3) * 2;
#pragma unroll
    for (int f = 0; f < 4; f++)
#pragma unroll
        for (int g = 0; g < 4; g++)
#pragma unroll
            for (int r = 0; r < 4; r++) {
                int Md = mb + f * 16 + ((r >> 1) << 3);
                int Ne = nb + g * 8 + (r & 1);
                wsplitB_half(g_Mh, g_Ml, Md, Ne, DD, acc[f][g][r]);
            }
}

// ===========================================================================
// Merged XM (z=0, 3-pass) + V projection (z=1, 2-pass, Vh out). grid (8,64,2).
// ===========================================================================
__global__ void __launch_bounds__(256, 2) k_xmv()
{
    const int row0 = blockIdx.y * 128;
    const int col0 = blockIdx.x * 128;
    const int lane = threadIdx.x & 31;
    const int wm   = (threadIdx.x >> 5) & 1;
    const int wn   = threadIdx.x >> 6;
    const int mb   = row0 + wm * 64 + (lane >> 2);
    const int nb   = col0 + wn * 32 + (lane & 3) * 2;

    if (blockIdx.z == 0) {
        ACC_DECL;
        mma_core<3>(g_Xh, g_Xl, row0, DD >> 4,
                    g_Mh, g_Ml, col0, DD >> 4, DD >> 5, acc);
#pragma unroll
        for (int f = 0; f < 4; f++)
#pragma unroll
            for (int g = 0; g < 4; g++) {
                int M0 = mb + f * 16;
                int N  = nb + g * 8;
                wsplitA_pair(g_XMh, g_XMl, M0,     N, DD, acc[f][g][0], acc[f][g][1]);
                wsplitA_pair(g_XMh, g_XMl, M0 + 8, N, DD, acc[f][g][2], acc[f][g][3]);
            }
    } else {
        ACC_DECL;
        mma_core<2>(g_Xh, g_Xl, row0, DD >> 4,
                    g_WvB, g_WvB, col0, DD >> 4, DD >> 5, acc);
#pragma unroll
        for (int f = 0; f < 4; f++)
#pragma unroll
            for (int g = 0; g < 4; g++)
#pragma unroll
                for (int r = 0; r < 4; r++) {
                    int Mg = mb + f * 16 + ((r >> 1) << 3);
                    int b  = Mg >> 11;
                    int sl = Mg & (TT - 1);
                    wB_half_h(g_Vh + (size_t)b * TT * DD / 2,
                              sl, nb + g * 8 + (r & 1), TT, acc[f][g][r]);
                }
    }
}

// ===========================================================================
// Scores S = (XM @ X^T)/32. Exact lower-tri 1D grid: 136 tiles x 4 batches.
// ===========================================================================
__global__ void __launch_bounds__(256, 2) k_scores()
{
    const int b = blockIdx.x / 136;
    int by, bx;
    tri_decode(blockIdx.x % 136, by, bx);
    const int row0 = b * TT + by * 128;
    const int col0 = b * TT + bx * 128;
    ACC_DECL;
    mma_core<3>(g_XMh, g_XMl, row0, DD >> 4,
                g_XBh, g_XBl, col0, DD >> 4, DD >> 5, acc);

    float* C = g_S + (size_t)b * TT * TT;
    const int lane = threadIdx.x & 31;
    const int wm   = (threadIdx.x >> 5) & 1;
    const int wn   = threadIdx.x >> 6;
    const int mb   = by * 128 + wm * 64 + (lane >> 2);
    const int nb   = bx * 128 + wn * 32 + (lane & 3) * 2;
#pragma unroll
    for (int f = 0; f < 4; f++)
#pragma unroll
        for (int g = 0; g < 4; g++)
#pragma unroll
            for (int r = 0; r < 4; r++) {
                int M = mb + f * 16 + ((r >> 1) << 3);
                int N = nb + g * 8 + (r & 1);
                C[(size_t)M * TT + N] = acc[f][g][r] * 0.03125f;
            }
}

// ===========================================================================
// Phase 1 softmax: per-row max and 1/sum. Longest rows first.
// ===========================================================================
__global__ void __launch_bounds__(256) k_rowstat()
{
    const int row = (blockIdx.x & ~(TT - 1)) | ((TT - 1) - (blockIdx.x & (TT - 1)));
    const int i   = row & (TT - 1);
    const float* s = g_S + (size_t)row * TT;
    const int L = i + 1;
    const int tid = threadIdx.x;
    __shared__ float red[256];

    float m = -CUDART_INF_F;
    for (int j = tid; j < L; j += 256) m = fmaxf(m, s[j]);
    red[tid] = m;
    __syncthreads();
    for (int w = 128; w > 0; w >>= 1) {
        if (tid < w) red[tid] = fmaxf(red[tid], red[tid + w]);
        __syncthreads();
    }
    m = red[0];
    __syncthreads();

    float sum = 0.0f;
    for (int j = tid; j < L; j += 256) sum += __expf(s[j] - m);
    red[tid] = sum;
    __syncthreads();
    for (int w = 128; w > 0; w >>= 1) {
        if (tid < w) red[tid] += red[tid + w];
        __syncthreads();
    }
    if (tid == 0) {
        g_rowM[row] = m;
        g_rowI[row] = 1.0f / red[0];
    }
}

// ===========================================================================
// Phase 2 softmax: coalesced A-layout region stores, h only. Heavy tiles first.
// ===========================================================================
__global__ void __launch_bounds__(256) k_wsplit()
{
    extern __shared__ float sws[];
    float* sS = sws;                    // 128 * 132
    float* sM = sws + 128 * 132;        // 128
    float* sI = sM + 128;               // 128

    const int b = blockIdx.x / 136;
    int by, bx;
    tri_decode(135 - (blockIdx.x % 136), by, bx);
    const int tid = threadIdx.x;
    const int row0 = by * 128;
    const int col0 = bx * 128;
    const float* S = g_S + (size_t)b * TT * TT;

    for (int i = tid; i < 4096; i += 256) {
        int r  = i >> 5;
        int c4 = (i & 31) << 2;
        float4 v = *(const float4*)(S + (size_t)(row0 + r) * TT + col0 + c4);
        sS[r * 132 + c4 + 0] = v.x;
        sS[r * 132 + c4 + 1] = v.y;
        sS[r * 132 + c4 + 2] = v.z;
        sS[r * 132 + c4 + 3] = v.w;
    }
    if (tid < 128) {
        sM[tid] = g_rowM[b * TT + row0 + tid];
        sI[tid] = g_rowI[b * TT + row0 + tid];
    }
    __syncthreads();

    const int w    = tid >> 5;
    const int lane = tid & 31;
    const bool diag = (bx == by);

    for (int kreg = 0; kreg < 8; kreg++) {
        const size_t Rg = ((size_t)(b * 128 + by * 8 + w)) * 128 + (size_t)(bx * 8 + kreg);
        uint32_t hv[4];
#pragma unroll
        for (int j = 0; j < 4; j++) {
            int m = w * 16 + (lane >> 2) + 8 * (j & 1);
            int k = kreg * 16 + (lane & 3) * 2 + 8 * ((j >> 1) & 1);
            float mx  = sM[m];
            float inv = sI[m];
            float w0 = __expf(sS[m * 132 + k]     - mx) * inv;
            float w1 = __expf(sS[m * 132 + k + 1] - mx) * inv;
            if (diag) {
                if (col0 + k     > row0 + m) w0 = 0.0f;
                if (col0 + k + 1 > row0 + m) w1 = 0.0f;
            }
            hv[j] = (uint32_t)__half_as_ushort(__float2half_rn(w0))
                  | ((uint32_t)__half_as_ushort(__float2half_rn(w1)) << 16);
        }
        *(uint4*)((uint32_t*)g_Sh + Rg * 128 + lane * 4) = make_uint4(hv[0], hv[1], hv[2], hv[3]);
    }
}

// ===========================================================================
// O = S_w * V, 1-pass (Wh * Vh), k clamped. Longest-first ordering.
// ===========================================================================
__global__ void __launch_bounds__(256, 2) k_pv(float* __restrict__ out)
{
    const int b    = blockIdx.z;
    const int by   = 15 - (int)blockIdx.y;     // heavy CTAs scheduled first
    const int row0 = b * TT + by * 128;
    const int col0 = blockIdx.x * 128;
    ACC_DECL;
    mma_core<1>(g_Sh, g_Sh, row0, TT >> 4,
                g_Vh + (size_t)b * TT * DD / 2, g_Vh + (size_t)b * TT * DD / 2,
                col0, TT >> 4, (by + 1) * 4, acc);

    float* C = out + (size_t)b * TT * DD;
    const int lane = threadIdx.x & 31;
    const int wm   = (threadIdx.x >> 5) & 1;
    const int wn   = threadIdx.x >> 6;
    const int mb   = by * 128 + wm * 64 + (lane >> 2);
    const int nb   = col0 + wn * 32 + (lane & 3) * 2;
#pragma unroll
    for (int f = 0; f < 4; f++)
#pragma unroll
        for (int g = 0; g < 4; g++)
#pragma unroll
            for (int r = 0; r < 4; r++) {
                int M = mb + f * 16 + ((r >> 1) << 3);
                int N = nb + g * 8 + (r & 1);
                C[(size_t)M * DD + N] = acc[f][g][r];
            }
}

// ===========================================================================
extern "C" void kernel_launch(void* const* d_in, const int* in_sizes, int n_in,
                              void* d_out, int out_size)
{
    const float* X  = (const float*)d_in[0];
    const float* Wq = (const float*)d_in[1];
    const float* Wk = (const float*)d_in[2];
    const float* Wv = (const float*)d_in[3];
    float* out = (float*)d_out;

    const int SMEMB = 98304;                       // 3 x 32KB mma buffers
    const int WSMEM = (128 * 132 + 256) * 4;       // 68,608 B
    cudaFuncSetAttribute(k_gemmM, cudaFuncAttributeMaxDynamicSharedMemorySize, SMEMB);
    cudaFuncSetAttribute(k_xmv,   cudaFuncAttributeMaxDynamicSharedMemorySize, SMEMB);
    cudaFuncSetAttribute(k_scores,cudaFuncAttributeMaxDynamicSharedMemorySize, SMEMB);
    cudaFuncSetAttribute(k_pv,    cudaFuncAttributeMaxDynamicSharedMemorySize, SMEMB);
    cudaFuncSetAttribute(k_wsplit,cudaFuncAttributeMaxDynamicSharedMemorySize, WSMEM);

    k_split  <<<12288, 256>>>(X, Wq, Wk, Wv);
    k_gemmM  <<<dim3(DD / 128, DD / 128), 256, SMEMB>>>();
    k_xmv    <<<dim3(DD / 128, (BB * TT) / 128, 2), 256, SMEMB>>>();
    k_scores <<<136 * BB, 256, SMEMB>>>();
    k_rowstat<<<BB * TT, 256>>>();
    k_wsplit <<<136 * BB, 256, WSMEM>>>();
    k_pv     <<<dim3(DD / 128, TT / 128, BB), 256, SMEMB>>>(out);
}

// round 16
// speedup vs baseline: 4.8339x; 1.0895x over previous
#include <cuda_runtime.h>
#include <cuda_fp16.h>
#include <math_constants.h>
#include <cstdint>

#define BB 4
#define TT 2048
#define DD 1024

// ============ scratch: fp16 hi/lo split arrays in mma fragment order =======
__device__ __half2 g_Xh [(size_t)BB * TT * DD / 2];   // X, A-layout
__device__ __half2 g_Xl [(size_t)BB * TT * DD / 2];
__device__ __half2 g_XBh[(size_t)BB * TT * DD / 2];   // X, B-layout
__device__ __half2 g_XBl[(size_t)BB * TT * DD / 2];
__device__ __half2 g_WqA[(size_t)DD * DD / 2];
__device__ __half2 g_WqAl[(size_t)DD * DD / 2];
__device__ __half2 g_WkB[(size_t)DD * DD / 2];
__device__ __half2 g_WkBl[(size_t)DD * DD / 2];
__device__ __half2 g_WvB[(size_t)DD * DD / 2];        // h only (V proj is 1-pass)
__device__ __half2 g_Mh [(size_t)DD * DD / 2];        // M = Wq Wk^T, B-layout
__device__ __half2 g_Ml [(size_t)DD * DD / 2];
__device__ __half2 g_XMh[(size_t)BB * TT * DD / 2];   // XM, A-layout
__device__ __half2 g_XMl[(size_t)BB * TT * DD / 2];
__device__ __half2 g_Vh [(size_t)BB * TT * DD / 2];   // V, B-layout per batch (h only)
__device__ float   g_S  [(size_t)BB * TT * TT];
__device__ __half2 g_Sh [(size_t)BB * TT * TT / 2];   // softmax weights, h only
__device__ float   g_rowM[(size_t)BB * TT];
__device__ float   g_rowI[(size_t)BB * TT];
__device__ float   g_tMax[(size_t)BB * 16 * 16 * 128];  // per-tile row stats
__device__ float   g_tSum[(size_t)BB * 16 * 16 * 128];

// ============================ helpers ======================================
__device__ __forceinline__ uint32_t smem_to_u32(const void* p) {
    uint32_t a;
    asm("{ .reg .u64 t; cvta.to.shared.u64 t, %1; cvt.u32.u64 %0, t; }"
        : "=r"(a) : "l"(p));
    return a;
}

__device__ __forceinline__ void mma16(float* d, uint4 a, uint2 b) {
    asm volatile(
        "mma.sync.aligned.m16n8k16.row.col.f32.f16.f16.f32 "
        "{%0,%1,%2,%3}, {%4,%5,%6,%7}, {%8,%9}, {%0,%1,%2,%3};"
        : "+f"(d[0]), "+f"(d[1]), "+f"(d[2]), "+f"(d[3])
        : "r"(a.x), "r"(a.y), "r"(a.z), "r"(a.w), "r"(b.x), "r"(b.y));
}

__device__ __forceinline__ size_t idxA32(int m, int k, int Kt) {
    return ((size_t)((m >> 4) * (Kt >> 4) + (k >> 4))) * 128
         + (size_t)((((m & 7) * 4 + ((k & 7) >> 1)) * 4)
                    + ((m >> 3) & 1) + (((k >> 3) & 1) << 1));
}
__device__ __forceinline__ size_t idxB32(int k, int n, int Kt) {
    return ((size_t)((n >> 3) * (Kt >> 4) + (k >> 4))) * 64
         + (size_t)((((n & 7) * 4 + ((k & 7) >> 1)) * 2) + ((k >> 3) & 1));
}

__device__ __forceinline__ void split1(float x, __half& h, __half& l) {
    h = __float2half_rn(x);
    l = __float2half_rn(x - __half2float(h));
}
__device__ __forceinline__ void wsplitA_pair(
    __half2* H, __half2* L, int m, int k, int Kt, float x0, float x1)
{
    __half h0, l0, h1, l1;
    split1(x0, h0, l0); split1(x1, h1, l1);
    size_t i = idxA32(m, k, Kt);
    H[i] = __halves2half2(h0, h1);
    L[i] = __halves2half2(l0, l1);
}
__device__ __forceinline__ void wsplitB_pair(
    __half2* H, __half2* L, int k, int n, int Kt, float x0, float x1)
{
    __half h0, l0, h1, l1;
    split1(x0, h0, l0); split1(x1, h1, l1);
    size_t i = idxB32(k, n, Kt);
    H[i] = __halves2half2(h0, h1);
    L[i] = __halves2half2(l0, l1);
}
__device__ __forceinline__ void wB_pair_h(
    __half2* H, int k, int n, int Kt, float x0, float x1)
{
    H[idxB32(k, n, Kt)] =
        __halves2half2(__float2half_rn(x0), __float2half_rn(x1));
}
__device__ __forceinline__ void wB_half_h(
    __half2* H, int k, int n, int Kt, float x)
{
    size_t i = idxB32(k, n, Kt) * 2 + (size_t)(k & 1);
    ((__half*)H)[i] = __float2half_rn(x);
}
__device__ __forceinline__ void wsplitB_half(
    __half2* H, __half2* L, int k, int n, int Kt, float x)
{
    __half h, l;
    split1(x, h, l);
    size_t i = idxB32(k, n, Kt) * 2 + (size_t)(k & 1);
    ((__half*)H)[i] = h;
    ((__half*)L)[i] = l;
}

__device__ __forceinline__ void cpasync16(uint32_t dst, const void* src) {
    asm volatile("cp.async.cg.shared.global [%0], [%1], 16;" :: "r"(dst), "l"(src));
}

// lower-triangular tile decode: t -> (by, bx), t = by*(by+1)/2 + bx, bx<=by
__device__ __forceinline__ void tri_decode(int t, int& by, int& bx) {
    int y = (int)((sqrtf(8.0f * (float)t + 1.0f) - 1.0f) * 0.5f);
    while ((y + 1) * (y + 2) / 2 <= t) y++;
    while (y * (y + 1) / 2 > t) y--;
    by = y;
    bx = t - y * (y + 1) / 2;
}

// ===========================================================================
// MMA core. NPASS=3: hh+lh+hl; NPASS=2: hh+lh; NPASS=1: hh.
// cp.async of Al only when NPASS>=2; of Bl only when NPASS==3.
// 3-stage pipeline, one barrier per chunk. 32KB/buffer.
// ===========================================================================
template<int NPASS>
__device__ __forceinline__ void mma_core(
    const __half2* __restrict__ Ah, const __half2* __restrict__ Al,
    int row0A, int aKt,
    const __half2* __restrict__ Bh, const __half2* __restrict__ Bl,
    int col0B, int bKt,
    int nchunks, float acc[4][4][4])
{
    extern __shared__ char smem[];
    const int tid  = threadIdx.x;
    const int lane = tid & 31;
    const int wm   = (tid >> 5) & 1;
    const int wn   = tid >> 6;
    const uint32_t sb_u32 = smem_to_u32(smem);

    const int aRB0 = (row0A >> 4) * aKt;
    const int bRB0 = (col0B >> 3) * bKt;

    auto copy_chunk = [&](int chunk) {
        const uint32_t sbase = sb_u32 + (uint32_t)(chunk % 3) * 32768u;
        for (int c = tid; c < 512; c += 256) {
            int rr = c >> 5;
            size_t off = (size_t)(aRB0 + (rr >> 1) * aKt + chunk * 2 + (rr & 1)) * 128
                       + (size_t)((c & 31) << 2);
            uint32_t d = sbase + (uint32_t)(c << 4);
            cpasync16(d, Ah + off);
            if (NPASS >= 2) cpasync16(d + 8192u, Al + off);
        }
        for (int c = tid; c < 512; c += 256) {
            int rr = c >> 4;
            size_t off = (size_t)(bRB0 + (rr >> 1) * bKt + chunk * 2 + (rr & 1)) * 64
                       + (size_t)((c & 15) << 2);
            uint32_t d = sbase + 16384u + (uint32_t)(c << 4);
            cpasync16(d, Bh + off);
            if (NPASS == 3) cpasync16(d + 8192u, Bl + off);
        }
        asm volatile("cp.async.commit_group;");
    };

    copy_chunk(0);
    if (nchunks > 1) copy_chunk(1);

    for (int t = 0; t < nchunks; t++) {
        if (t + 1 < nchunks) asm volatile("cp.async.wait_group 1;");
        else                 asm volatile("cp.async.wait_group 0;");
        __syncthreads();

        if (t + 2 < nchunks) copy_chunk(t + 2);

        const char* sb = smem + (size_t)(t % 3) * 32768;
        const uint4* pAh = (const uint4*)sb;
        const uint4* pAl = (const uint4*)(sb + 8192);
        const uint2* pBh = (const uint2*)(sb + 16384);
        const uint2* pBl = (const uint2*)(sb + 24576);

#pragma unroll
        for (int ki = 0; ki < 2; ki++) {
            uint4 fAh[4]; uint2 fBh[4];
#pragma unroll
            for (int f = 0; f < 4; f++)
                fAh[f] = pAh[((wm * 4 + f) * 2 + ki) * 32 + lane];
#pragma unroll
            for (int g = 0; g < 4; g++)
                fBh[g] = pBh[((wn * 4 + g) * 2 + ki) * 32 + lane];
#pragma unroll
            for (int f = 0; f < 4; f++)
#pragma unroll
                for (int g = 0; g < 4; g++) mma16(acc[f][g], fAh[f], fBh[g]);
            if (NPASS >= 2) {
                uint4 fAl[4];
#pragma unroll
                for (int f = 0; f < 4; f++)
                    fAl[f] = pAl[((wm * 4 + f) * 2 + ki) * 32 + lane];
#pragma unroll
                for (int f = 0; f < 4; f++)
#pragma unroll
                    for (int g = 0; g < 4; g++) mma16(acc[f][g], fAl[f], fBh[g]);
            }
            if (NPASS == 3) {
                uint2 fBl[4];
#pragma unroll
                for (int g = 0; g < 4; g++)
                    fBl[g] = pBl[((wn * 4 + g) * 2 + ki) * 32 + lane];
#pragma unroll
                for (int f = 0; f < 4; f++)
#pragma unroll
                    for (int g = 0; g < 4; g++) mma16(acc[f][g], fAh[f], fBl[g]);
            }
        }
    }
    __syncthreads();
}
// acc coords: m = wm*64 + f*16 + (lane>>2) + 8*(r>>1); n = wn*32 + g*8 + (lane&3)*2 + (r&1)

#define ACC_DECL float acc[4][4][4]; \
    _Pragma("unroll") for (int f = 0; f < 4; f++) \
    _Pragma("unroll") for (int g = 0; g < 4; g++) \
    _Pragma("unroll") for (int r = 0; r < 4; r++) acc[f][g][r] = 0.0f;

// ===========================================================================
// Merged splits: one launch.
// ===========================================================================
__global__ void __launch_bounds__(256) k_split(
    const float* __restrict__ X,  const float* __restrict__ Wq,
    const float* __restrict__ Wk, const float* __restrict__ Wv)
{
    const int bid = blockIdx.x;
    const int tid = threadIdx.x;
    if (bid < 8192) {
        int i = bid * 256 + tid;
        int m  = i >> 8;
        int d0 = (i & 255) << 2;
        float4 v = *(const float4*)(X + (size_t)m * DD + d0);
        wsplitA_pair(g_Xh,  g_Xl,  m, d0,     DD, v.x, v.y);
        wsplitA_pair(g_Xh,  g_Xl,  m, d0 + 2, DD, v.z, v.w);
        wsplitB_pair(g_XBh, g_XBl, d0,     m, DD, v.x, v.y);
        wsplitB_pair(g_XBh, g_XBl, d0 + 2, m, DD, v.z, v.w);
    } else if (bid < 9216) {
        int i = (bid - 8192) * 256 + tid;
        int d  = i >> 8;
        int j0 = (i & 255) << 2;
        float4 v = *(const float4*)(Wq + (size_t)d * DD + j0);
        wsplitA_pair(g_WqA, g_WqAl, d, j0,     DD, v.x, v.y);
        wsplitA_pair(g_WqA, g_WqAl, d, j0 + 2, DD, v.z, v.w);
    } else if (bid < 10240) {
        int i = (bid - 9216) * 256 + tid;
        int e  = i >> 8;
        int j0 = (i & 255) << 2;
        float4 v = *(const float4*)(Wk + (size_t)e * DD + j0);
        wsplitB_pair(g_WkB, g_WkBl, j0,     e, DD, v.x, v.y);
        wsplitB_pair(g_WkB, g_WkBl, j0 + 2, e, DD, v.z, v.w);
    } else {
        int i = (bid - 10240) * 256 + tid;
        int r2 = (i >> 10) << 1;
        int c  = i & 1023;
        float x0 = Wv[(size_t)r2 * DD + c];
        float x1 = Wv[(size_t)(r2 + 1) * DD + c];
        wB_pair_h(g_WvB, r2, c, DD, x0, x1);   // h only: V proj is 1-pass
    }
}

// ===========================================================================
// M = Wq @ Wk^T. grid (8, 8). 3-pass (precision-critical).
// ===========================================================================
__global__ void __launch_bounds__(256, 2) k_gemmM()
{
    const int row0 = blockIdx.y * 128;
    const int col0 = blockIdx.x * 128;
    ACC_DECL;
    mma_core<3>(g_WqA, g_WqAl, row0, DD >> 4,
                g_WkB, g_WkBl, col0, DD >> 4, DD >> 5, acc);

    const int lane = threadIdx.x & 31;
    const int wm   = (threadIdx.x >> 5) & 1;
    const int wn   = threadIdx.x >> 6;
    const int mb   = row0 + wm * 64 + (lane >> 2);
    const int nb   = col0 + wn * 32 + (lane & 3) * 2;
#pragma unroll
    for (int f = 0; f < 4; f++)
#pragma unroll
        for (int g = 0; g < 4; g++)
#pragma unroll
            for (int r = 0; r < 4; r++) {
                int Md = mb + f * 16 + ((r >> 1) << 3);
                int Ne = nb + g * 8 + (r & 1);
                wsplitB_half(g_Mh, g_Ml, Md, Ne, DD, acc[f][g][r]);
            }
}

// ===========================================================================
// Merged XM (z=0, 3-pass) + V projection (z=1, 1-pass, Vh out). grid (8,64,2).
// ===========================================================================
__global__ void __launch_bounds__(256, 2) k_xmv()
{
    const int row0 = blockIdx.y * 128;
    const int col0 = blockIdx.x * 128;
    const int lane = threadIdx.x & 31;
    const int wm   = (threadIdx.x >> 5) & 1;
    const int wn   = threadIdx.x >> 6;
    const int mb   = row0 + wm * 64 + (lane >> 2);
    const int nb   = col0 + wn * 32 + (lane & 3) * 2;

    if (blockIdx.z == 0) {
        ACC_DECL;
        mma_core<3>(g_Xh, g_Xl, row0, DD >> 4,
                    g_Mh, g_Ml, col0, DD >> 4, DD >> 5, acc);
#pragma unroll
        for (int f = 0; f < 4; f++)
#pragma unroll
            for (int g = 0; g < 4; g++) {
                int M0 = mb + f * 16;
                int N  = nb + g * 8;
                wsplitA_pair(g_XMh, g_XMl, M0,     N, DD, acc[f][g][0], acc[f][g][1]);
                wsplitA_pair(g_XMh, g_XMl, M0 + 8, N, DD, acc[f][g][2], acc[f][g][3]);
            }
    } else {
        ACC_DECL;
        mma_core<1>(g_Xh, g_Xh, row0, DD >> 4,
                    g_WvB, g_WvB, col0, DD >> 4, DD >> 5, acc);
#pragma unroll
        for (int f = 0; f < 4; f++)
#pragma unroll
            for (int g = 0; g < 4; g++)
#pragma unroll
                for (int r = 0; r < 4; r++) {
                    int Mg = mb + f * 16 + ((r >> 1) << 3);
                    int b  = Mg >> 11;
                    int sl = Mg & (TT - 1);
                    wB_half_h(g_Vh + (size_t)b * TT * DD / 2,
                              sl, nb + g * 8 + (r & 1), TT, acc[f][g][r]);
                }
    }
}

// ===========================================================================
// Scores S = (XM @ X^T)/32 + fused per-tile row stats (max, exp-sum).
// Exact lower-tri 1D grid: 136 tiles x 4 batches.
// ===========================================================================
__global__ void __launch_bounds__(256, 2) k_scores()
{
    extern __shared__ char smem[];
    const int b = blockIdx.x / 136;
    int by, bx;
    tri_decode(blockIdx.x % 136, by, bx);
    const int row0 = b * TT + by * 128;
    const int col0 = b * TT + bx * 128;
    ACC_DECL;
    mma_core<3>(g_XMh, g_XMl, row0, DD >> 4,
                g_XBh, g_XBl, col0, DD >> 4, DD >> 5, acc);
    // mma_core ends with __syncthreads -> smem reusable for stats

    float* C = g_S + (size_t)b * TT * TT;
    const int tid  = threadIdx.x;
    const int lane = tid & 31;
    const int wm   = (tid >> 5) & 1;
    const int wn   = tid >> 6;
    const bool diag = (bx == by);

    float* pM  = (float*)smem;          // [128][4]
    float* pS  = pM + 512;              // [128][4]
    float* rM2 = pS + 512;              // [128]

    // pass 1: scale, store S, per-thread masked row-max
#pragma unroll
    for (int f = 0; f < 4; f++) {
#pragma unroll
        for (int rh = 0; rh < 2; rh++) {
            const int Mloc = wm * 64 + f * 16 + (lane >> 2) + rh * 8;
            const int Mg   = by * 128 + Mloc;
            float mymax = -CUDART_INF_F;
#pragma unroll
            for (int g = 0; g < 4; g++)
#pragma unroll
                for (int c01 = 0; c01 < 2; c01++) {
                    float val = acc[f][g][rh * 2 + c01] * 0.03125f;
                    acc[f][g][rh * 2 + c01] = val;
                    int Ng = bx * 128 + wn * 32 + (lane & 3) * 2 + g * 8 + c01;
                    C[(size_t)Mg * TT + Ng] = val;
                    if (!diag || Ng <= Mg) mymax = fmaxf(mymax, val);
                }
            mymax = fmaxf(mymax, __shfl_xor_sync(0xffffffffu, mymax, 1));
            mymax = fmaxf(mymax, __shfl_xor_sync(0xffffffffu, mymax, 2));
            if ((lane & 3) == 0) pM[Mloc * 4 + wn] = mymax;
        }
    }
    __syncthreads();
    if (tid < 128) {
        float a0 = fmaxf(pM[tid * 4 + 0], pM[tid * 4 + 1]);
        float a1 = fmaxf(pM[tid * 4 + 2], pM[tid * 4 + 3]);
        rM2[tid] = fmaxf(a0, a1);
    }
    __syncthreads();

    // pass 2: exp-sum vs tile row-max
#pragma unroll
    for (int f = 0; f < 4; f++) {
#pragma unroll
        for (int rh = 0; rh < 2; rh++) {
            const int Mloc = wm * 64 + f * 16 + (lane >> 2) + rh * 8;
            const int Mg   = by * 128 + Mloc;
            const float rm = rM2[Mloc];
            float s = 0.0f;
#pragma unroll
            for (int g = 0; g < 4; g++)
#pragma unroll
                for (int c01 = 0; c01 < 2; c01++) {
                    int Ng = bx * 128 + wn * 32 + (lane & 3) * 2 + g * 8 + c01;
                    if (!diag || Ng <= Mg)
                        s += __expf(acc[f][g][rh * 2 + c01] - rm);
                }
            s += __shfl_xor_sync(0xffffffffu, s, 1);
            s += __shfl_xor_sync(0xffffffffu, s, 2);
            if ((lane & 3) == 0) pS[Mloc * 4 + wn] = s;
        }
    }
    __syncthreads();
    if (tid < 128) {
        float ssum = pS[tid * 4] + pS[tid * 4 + 1] + pS[tid * 4 + 2] + pS[tid * 4 + 3];
        size_t idx = ((size_t)(b * 16 + by) * 16 + bx) * 128 + tid;
        g_tMax[idx] = rM2[tid];
        g_tSum[idx] = ssum;
    }
}

// ===========================================================================
// Combine per-tile stats -> per-row (max, 1/sum). grid 32 x 256 (8192 rows).
// ===========================================================================
__global__ void __launch_bounds__(256) k_rowstat2()
{
    const int row = blockIdx.x * 256 + threadIdx.x;
    const int b   = row >> 11;
    const int ib  = row & (TT - 1);
    const int by  = ib >> 7;
    const int rl  = ib & 127;

    float gm = -CUDART_INF_F;
    for (int bx = 0; bx <= by; bx++)
        gm = fmaxf(gm, g_tMax[((size_t)(b * 16 + by) * 16 + bx) * 128 + rl]);
    float sum = 0.0f;
    for (int bx = 0; bx <= by; bx++) {
        size_t idx = ((size_t)(b * 16 + by) * 16 + bx) * 128 + rl;
        sum += __expf(g_tMax[idx] - gm) * g_tSum[idx];
    }
    g_rowM[row] = gm;
    g_rowI[row] = 1.0f / sum;
}

// ===========================================================================
// Softmax weights: coalesced A-layout region stores, h only. Heavy tiles first.
// ===========================================================================
__global__ void __launch_bounds__(256) k_wsplit()
{
    extern __shared__ float sws[];
    float* sS = sws;                    // 128 * 132
    float* sM = sws + 128 * 132;        // 128
    float* sI = sM + 128;               // 128

    const int b = blockIdx.x / 136;
    int by, bx;
    tri_decode(135 - (blockIdx.x % 136), by, bx);
    const int tid = threadIdx.x;
    const int row0 = by * 128;
    const int col0 = bx * 128;
    const float* S = g_S + (size_t)b * TT * TT;

    for (int i = tid; i < 4096; i += 256) {
        int r  = i >> 5;
        int c4 = (i & 31) << 2;
        float4 v = *(const float4*)(S + (size_t)(row0 + r) * TT + col0 + c4);
        sS[r * 132 + c4 + 0] = v.x;
        sS[r * 132 + c4 + 1] = v.y;
        sS[r * 132 + c4 + 2] = v.z;
        sS[r * 132 + c4 + 3] = v.w;
    }
    if (tid < 128) {
        sM[tid] = g_rowM[b * TT + row0 + tid];
        sI[tid] = g_rowI[b * TT + row0 + tid];
    }
    __syncthreads();

    const int w    = tid >> 5;
    const int lane = tid & 31;
    const bool diag = (bx == by);

    for (int kreg = 0; kreg < 8; kreg++) {
        const size_t Rg = ((size_t)(b * 128 + by * 8 + w)) * 128 + (size_t)(bx * 8 + kreg);
        uint32_t hv[4];
#pragma unroll
        for (int j = 0; j < 4; j++) {
            int m = w * 16 + (lane >> 2) + 8 * (j & 1);
            int k = kreg * 16 + (lane & 3) * 2 + 8 * ((j >> 1) & 1);
            float mx  = sM[m];
            float inv = sI[m];
            float w0 = __expf(sS[m * 132 + k]     - mx) * inv;
            float w1 = __expf(sS[m * 132 + k + 1] - mx) * inv;
            if (diag) {
                if (col0 + k     > row0 + m) w0 = 0.0f;
                if (col0 + k + 1 > row0 + m) w1 = 0.0f;
            }
            hv[j] = (uint32_t)__half_as_ushort(__float2half_rn(w0))
                  | ((uint32_t)__half_as_ushort(__float2half_rn(w1)) << 16);
        }
        *(uint4*)((uint32_t*)g_Sh + Rg * 128 + lane * 4) = make_uint4(hv[0], hv[1], hv[2], hv[3]);
    }
}

// ===========================================================================
// O = S_w * V, 1-pass (Wh * Vh), k clamped. Longest-first ordering.
// ===========================================================================
__global__ void __launch_bounds__(256, 2) k_pv(float* __restrict__ out)
{
    const int b    = blockIdx.z;
    const int by   = 15 - (int)blockIdx.y;     // heavy CTAs scheduled first
    const int row0 = b * TT + by * 128;
    const int col0 = blockIdx.x * 128;
    ACC_DECL;
    mma_core<1>(g_Sh, g_Sh, row0, TT >> 4,
                g_Vh + (size_t)b * TT * DD / 2, g_Vh + (size_t)b * TT * DD / 2,
                col0, TT >> 4, (by + 1) * 4, acc);

    float* C = out + (size_t)b * TT * DD;
    const int lane = threadIdx.x & 31;
    const int wm   = (threadIdx.x >> 5) & 1;
    const int wn   = threadIdx.x >> 6;
    const int mb   = by * 128 + wm * 64 + (lane >> 2);
    const int nb   = col0 + wn * 32 + (lane & 3) * 2;
#pragma unroll
    for (int f = 0; f < 4; f++)
#pragma unroll
        for (int g = 0; g < 4; g++)
#pragma unroll
            for (int r = 0; r < 4; r++) {
                int M = mb + f * 16 + ((r >> 1) << 3);
                int N = nb + g * 8 + (r & 1);
                C[(size_t)M * DD + N] = acc[f][g][r];
            }
}

// ===========================================================================
extern "C" void kernel_launch(void* const* d_in, const int* in_sizes, int n_in,
                              void* d_out, int out_size)
{
    const float* X  = (const float*)d_in[0];
    const float* Wq = (const float*)d_in[1];
    const float* Wk = (const float*)d_in[2];
    const float* Wv = (const float*)d_in[3];
    float* out = (float*)d_out;

    const int SMEMB = 98304;                       // 3 x 32KB mma buffers
    const int WSMEM = (128 * 132 + 256) * 4;       // 68,608 B
    cudaFuncSetAttribute(k_gemmM, cudaFuncAttributeMaxDynamicSharedMemorySize, SMEMB);
    cudaFuncSetAttribute(k_xmv,   cudaFuncAttributeMaxDynamicSharedMemorySize, SMEMB);
    cudaFuncSetAttribute(k_scores,cudaFuncAttributeMaxDynamicSharedMemorySize, SMEMB);
    cudaFuncSetAttribute(k_pv,    cudaFuncAttributeMaxDynamicSharedMemorySize, SMEMB);
    cudaFuncSetAttribute(k_wsplit,cudaFuncAttributeMaxDynamicSharedMemorySize, WSMEM);

    k_split   <<<12288, 256>>>(X, Wq, Wk, Wv);
    k_gemmM   <<<dim3(DD / 128, DD / 128), 256, SMEMB>>>();
    k_xmv     <<<dim3(DD / 128, (BB * TT) / 128, 2), 256, SMEMB>>>();
    k_scores  <<<136 * BB, 256, SMEMB>>>();
    k_rowstat2<<<(BB * TT) / 256, 256>>>();
    k_wsplit  <<<136 * BB, 256, WSMEM>>>();
    k_pv      <<<dim3(DD / 128, TT / 128, BB), 256, SMEMB>>>(out);
}